// round 2
// baseline (speedup 1.0000x reference)
#include <cuda_runtime.h>
#include <cstddef>

// Problem constants
#define NB    4
#define NQ    2048
#define DQ    512
#define NKK   1024
#define DC    768
#define NHEAD 8
#define DHEAD 64
#define INNER 512   // NHEAD*DHEAD

// Scratch buffers (device globals — no allocation allowed)
__device__ float g_Q [NB * NQ  * INNER];   // 16 MB
__device__ float g_K [NB * NKK * INNER];   //  8 MB
__device__ float g_V [NB * NKK * INNER];   //  8 MB
__device__ float g_AO[NB * NQ  * INNER];   // 16 MB

// ---------------------------------------------------------------------------
// Generic tiled fp32 GEMM: C[M,N] = A[M,K] @ W[K,N] (+ bias)
// 64x64 tile, BK=16, 256 threads, 4x4 per-thread micro-tile.
// All dims used here are multiples of the tile sizes: no bounds checks.
// ---------------------------------------------------------------------------
template <bool BIAS>
__global__ __launch_bounds__(256) void gemm64_kernel(
    const float* __restrict__ A, const float* __restrict__ W,
    const float* __restrict__ bias, float* __restrict__ C,
    int M, int K, int N)
{
    __shared__ float As[64][17];   // [row][k]  pad 17 (row-broadcast reads)
    __shared__ float Bs[16][65];   // [k][col]  pad 65 (<=2-way conflicts)

    const int tid = threadIdx.x;
    const int tx = tid & 15, ty = tid >> 4;
    const int r0 = ty * 4, c0 = tx * 4;
    const int m0 = blockIdx.y * 64, n0 = blockIdx.x * 64;

    float acc[4][4] = {};

    for (int k0 = 0; k0 < K; k0 += 16) {
        #pragma unroll
        for (int i = 0; i < 4; i++) {              // A tile: 64x16
            int id = tid + i * 256;
            int r = id >> 4, c = id & 15;
            As[r][c] = A[(size_t)(m0 + r) * K + (k0 + c)];
        }
        #pragma unroll
        for (int i = 0; i < 4; i++) {              // B tile: 16x64
            int id = tid + i * 256;
            int r = id >> 6, c = id & 63;
            Bs[r][c] = W[(size_t)(k0 + r) * N + (n0 + c)];
        }
        __syncthreads();

        #pragma unroll
        for (int k = 0; k < 16; k++) {
            float a[4], b[4];
            #pragma unroll
            for (int i = 0; i < 4; i++) a[i] = As[r0 + i][k];
            #pragma unroll
            for (int j = 0; j < 4; j++) b[j] = Bs[k][c0 + j];
            #pragma unroll
            for (int i = 0; i < 4; i++)
                #pragma unroll
                for (int j = 0; j < 4; j++)
                    acc[i][j] = fmaf(a[i], b[j], acc[i][j]);
        }
        __syncthreads();
    }

    #pragma unroll
    for (int i = 0; i < 4; i++) {
        #pragma unroll
        for (int j = 0; j < 4; j++) {
            float v = acc[i][j];
            if (BIAS) v += bias[n0 + c0 + j];
            C[(size_t)(m0 + r0 + i) * N + (n0 + c0 + j)] = v;
        }
    }
}

// ---------------------------------------------------------------------------
// Fused flash attention (fp32, online softmax).
// Block = (q-tile of 64, one (b,h)); 256 threads, 4x4 micro-tiles.
// smem: Qs[64x65], KVs[64x65] (K then V), Ss[64x65], row-state m/l/r.
// ---------------------------------------------------------------------------
__global__ __launch_bounds__(256) void attn_kernel(float* __restrict__ AO)
{
    extern __shared__ float sm[];
    float* Qs   = sm;                 // [q][d]   stride 65
    float* KVs  = sm + 64 * 65;       // [key][d] stride 65
    float* Ss   = sm + 2 * 64 * 65;   // [q][k]   stride 65
    float* mrow = sm + 3 * 64 * 65;   // [64]
    float* lrow = mrow + 64;          // [64]
    float* rrow = lrow + 64;          // [64]

    const int tid = threadIdx.x;
    const int tx = tid & 15, ty = tid >> 4;
    const int r0 = ty * 4, c0 = tx * 4;

    const int qt = blockIdx.x;              // 0..31 (q tile)
    const int bh = blockIdx.y;              // 0..31
    const int b  = bh >> 3, h = bh & 7;

    const float* Qp = g_Q + ((size_t)(b * NQ  + qt * 64)) * INNER + h * DHEAD;
    const float* Kp = g_K + ((size_t)(b * NKK)) * INNER + h * DHEAD;
    const float* Vp = g_V + ((size_t)(b * NKK)) * INNER + h * DHEAD;

    // Load Q tile [64 q][64 d]
    #pragma unroll
    for (int i = 0; i < 16; i++) {
        int id = tid + i * 256;
        int r = id >> 6, c = id & 63;
        Qs[r * 65 + c] = Qp[(size_t)r * INNER + c];
    }
    if (tid < 64) { mrow[tid] = -1e30f; lrow[tid] = 0.f; }

    float acc[4][4] = {};
    __syncthreads();

    for (int kt = 0; kt < NKK / 64; kt++) {
        // Load K tile [64 key][64 d]
        #pragma unroll
        for (int i = 0; i < 16; i++) {
            int id = tid + i * 256;
            int r = id >> 6, c = id & 63;
            KVs[r * 65 + c] = Kp[((size_t)(kt * 64 + r)) * INNER + c];
        }
        __syncthreads();

        // S = Q @ K^T * scale
        float s[4][4] = {};
        #pragma unroll 4
        for (int d = 0; d < 64; d++) {
            float a[4], bb[4];
            #pragma unroll
            for (int i = 0; i < 4; i++) a[i]  = Qs [(r0 + i) * 65 + d];
            #pragma unroll
            for (int j = 0; j < 4; j++) bb[j] = KVs[(c0 + j) * 65 + d];
            #pragma unroll
            for (int i = 0; i < 4; i++)
                #pragma unroll
                for (int j = 0; j < 4; j++)
                    s[i][j] = fmaf(a[i], bb[j], s[i][j]);
        }
        #pragma unroll
        for (int i = 0; i < 4; i++)
            #pragma unroll
            for (int j = 0; j < 4; j++)
                Ss[(r0 + i) * 65 + (c0 + j)] = s[i][j] * 0.125f;  // scale = 64^-0.5
        __syncthreads();   // Ss complete; all K reads done

        // Load V tile (overwrites KVs) — overlaps softmax below
        #pragma unroll
        for (int i = 0; i < 16; i++) {
            int id = tid + i * 256;
            int r = id >> 6, c = id & 63;
            KVs[r * 65 + c] = Vp[((size_t)(kt * 64 + r)) * INNER + c];
        }

        // Online softmax: thread i owns q-row i
        if (tid < 64) {
            const int row = tid;
            float mo = mrow[row], mx = mo;
            #pragma unroll 8
            for (int k = 0; k < 64; k++) mx = fmaxf(mx, Ss[row * 65 + k]);
            float rsc = __expf(mo - mx);
            float sum = 0.f;
            #pragma unroll 8
            for (int k = 0; k < 64; k++) {
                float p = __expf(Ss[row * 65 + k] - mx);
                Ss[row * 65 + k] = p;
                sum += p;
            }
            lrow[row] = lrow[row] * rsc + sum;
            mrow[row] = mx;
            rrow[row] = rsc;
        }
        __syncthreads();   // V + P + rescale factors ready

        // Rescale accumulators, then O += P @ V
        #pragma unroll
        for (int i = 0; i < 4; i++) {
            float rs = rrow[r0 + i];
            #pragma unroll
            for (int j = 0; j < 4; j++) acc[i][j] *= rs;
        }
        #pragma unroll 4
        for (int k = 0; k < 64; k++) {
            float a[4], bb[4];
            #pragma unroll
            for (int i = 0; i < 4; i++) a[i]  = Ss [(r0 + i) * 65 + k];
            #pragma unroll
            for (int j = 0; j < 4; j++) bb[j] = KVs[k * 65 + (c0 + j)];
            #pragma unroll
            for (int i = 0; i < 4; i++)
                #pragma unroll
                for (int j = 0; j < 4; j++)
                    acc[i][j] = fmaf(a[i], bb[j], acc[i][j]);
        }
        __syncthreads();   // KVs free for next K tile
    }

    // Epilogue: normalize and store to g_AO (layout [B*Nq, h*64+d])
    #pragma unroll
    for (int i = 0; i < 4; i++) {
        float inv = 1.f / lrow[r0 + i];
        const size_t base = ((size_t)(b * NQ + qt * 64 + r0 + i)) * INNER + h * DHEAD;
        #pragma unroll
        for (int j = 0; j < 4; j++)
            AO[base + c0 + j] = acc[i][j] * inv;
    }
}

// ---------------------------------------------------------------------------
// Launcher: 5 kernels — Q/K/V proj, fused attention, output proj (+bias)
// ---------------------------------------------------------------------------
extern "C" void kernel_launch(void* const* d_in, const int* in_sizes, int n_in,
                              void* d_out, int out_size)
{
    const float* x   = (const float*)d_in[0];  // [4,2048,512]
    const float* ctx = (const float*)d_in[1];  // [4,1024,768]
    const float* Wq  = (const float*)d_in[2];  // [512,512]
    const float* Wk  = (const float*)d_in[3];  // [768,512]
    const float* Wv  = (const float*)d_in[4];  // [768,512]
    const float* Wo  = (const float*)d_in[5];  // [512,512]
    const float* bo  = (const float*)d_in[6];  // [512]
    float* out = (float*)d_out;

    float *Qb, *Kb, *Vb, *AOb;
    cudaGetSymbolAddress((void**)&Qb,  g_Q);
    cudaGetSymbolAddress((void**)&Kb,  g_K);
    cudaGetSymbolAddress((void**)&Vb,  g_V);
    cudaGetSymbolAddress((void**)&AOb, g_AO);

    const int ATTN_SMEM = (3 * 64 * 65 + 3 * 64) * (int)sizeof(float);  // 50688
    cudaFuncSetAttribute(attn_kernel,
                         cudaFuncAttributeMaxDynamicSharedMemorySize, ATTN_SMEM);

    // Q = x @ Wq : [8192,512] x [512,512]
    gemm64_kernel<false><<<dim3(INNER / 64, (NB * NQ) / 64), 256>>>(
        x, Wq, nullptr, Qb, NB * NQ, DQ, INNER);
    // K = ctx @ Wk : [4096,768] x [768,512]
    gemm64_kernel<false><<<dim3(INNER / 64, (NB * NKK) / 64), 256>>>(
        ctx, Wk, nullptr, Kb, NB * NKK, DC, INNER);
    // V = ctx @ Wv
    gemm64_kernel<false><<<dim3(INNER / 64, (NB * NKK) / 64), 256>>>(
        ctx, Wv, nullptr, Vb, NB * NKK, DC, INNER);
    // Fused attention
    attn_kernel<<<dim3(NQ / 64, NB * NHEAD), 256, ATTN_SMEM>>>(AOb);
    // out = AO @ Wo + bo
    gemm64_kernel<true><<<dim3(DQ / 64, (NB * NQ) / 64), 256>>>(
        AOb, Wo, bo, out, NB * NQ, INNER, DQ);
}

// round 5
// speedup vs baseline: 1.7087x; 1.7087x over previous
#include <cuda_runtime.h>
#include <cuda_bf16.h>
#include <cstdint>
#include <cstddef>

// Problem constants
#define NB    4
#define NQ    2048
#define DQ    512
#define NKK   1024
#define DC    768
#define NHEAD 8
#define DHEAD 64
#define INNER 512   // NHEAD*DHEAD

// ---------------------------------------------------------------------------
// Scratch (device globals — no allocation allowed)
// ---------------------------------------------------------------------------
__device__ float g_Q [NB * NQ  * INNER];
__device__ float g_K [NB * NKK * INNER];
__device__ float g_V [NB * NKK * INNER];
__device__ float g_AO[NB * NQ  * INNER];

// transposed + split weights: WT[n][k] = W[k][n]
__device__ __nv_bfloat16 g_WqTh[INNER * DQ],  g_WqTl[INNER * DQ];
__device__ __nv_bfloat16 g_WkTh[INNER * DC],  g_WkTl[INNER * DC];
__device__ __nv_bfloat16 g_WvTh[INNER * DC],  g_WvTl[INNER * DC];
__device__ __nv_bfloat16 g_WoTh[DQ * INNER],  g_WoTl[DQ * INNER];

// ---------------------------------------------------------------------------
// Transpose + split: W[K][N] -> WT hi/lo [N][K]
// ---------------------------------------------------------------------------
__global__ void splitT_kernel(const float* __restrict__ W,
                              __nv_bfloat16* __restrict__ hT,
                              __nv_bfloat16* __restrict__ lT,
                              int K, int N)
{
    __shared__ float t[32][33];
    const int n0 = blockIdx.x * 32, k0 = blockIdx.y * 32;
    const int tx = threadIdx.x, ty = threadIdx.y;
    #pragma unroll
    for (int r = ty; r < 32; r += 8)
        t[r][tx] = W[(size_t)(k0 + r) * N + n0 + tx];
    __syncthreads();
    #pragma unroll
    for (int r = ty; r < 32; r += 8) {
        float v = t[tx][r];               // element (n = n0+r, k = k0+tx)
        __nv_bfloat16 h = __float2bfloat16(v);
        size_t idx = (size_t)(n0 + r) * K + k0 + tx;
        hT[idx] = h;
        lT[idx] = __float2bfloat16(v - __bfloat162float(h));
    }
}

// ---------------------------------------------------------------------------
// HMMA bf16-split GEMM: C[M,N] = A[M,K](fp32, split in-kernel) @ B^T,
// B stored [N,K] as pre-split bf16 hi/lo. 128x128 CTA tile, BK=32,
// 8 warps (2m x 4n), warp tile 64x32, mma.m16n8k16, fp32 accumulate.
// smem rows padded to 20 words (40 bf16) -> conflict-free fragment LDS.
// Register-prefetch pipeline hides LDG latency (single smem buffer).
// ---------------------------------------------------------------------------
#define GROW 20   // words per smem row (40 bf16 = 80B)

#define MMA_BF16(d, a, b0, b1) \
    asm volatile("mma.sync.aligned.m16n8k16.row.col.f32.bf16.bf16.f32 " \
        "{%0,%1,%2,%3}, {%4,%5,%6,%7}, {%8,%9}, {%0,%1,%2,%3};" \
        : "+f"((d)[0]), "+f"((d)[1]), "+f"((d)[2]), "+f"((d)[3]) \
        : "r"((a)[0]), "r"((a)[1]), "r"((a)[2]), "r"((a)[3]), \
          "r"(b0), "r"(b1))

__global__ __launch_bounds__(256, 1) void hgemm_kernel(
    const float* __restrict__ A,
    const __nv_bfloat16* __restrict__ Bh, const __nv_bfloat16* __restrict__ Bl,
    const float* __restrict__ bias, float* __restrict__ C,
    int M, int K, int N)
{
    __shared__ __align__(16) uint32_t sAh[128 * GROW];
    __shared__ __align__(16) uint32_t sAl[128 * GROW];
    __shared__ __align__(16) uint32_t sBh[128 * GROW];
    __shared__ __align__(16) uint32_t sBl[128 * GROW];

    const int tid  = threadIdx.x;
    const int lane = tid & 31, wid = tid >> 5;
    const int wm = (wid >> 2) * 64;     // warp m base: 0 or 64
    const int wn = (wid & 3) * 32;      // warp n base: 0..96
    const int g  = lane >> 2, tg = lane & 3;
    const int m0 = blockIdx.y * 128, n0 = blockIdx.x * 128;

    const int nch = K >> 5;

    float4 pa[4];
    uint4  pbh[2], pbl[2];

    // prefetch chunk 0
    {
        const int k0 = 0;
        #pragma unroll
        for (int i = 0; i < 4; i++) {
            int id = tid + i * 256;
            int r = id >> 3, c4 = id & 7;
            pa[i] = *reinterpret_cast<const float4*>(A + (size_t)(m0 + r) * K + k0 + c4 * 4);
        }
        #pragma unroll
        for (int i = 0; i < 2; i++) {
            int id = tid + i * 256;
            int r = id >> 2, gg = id & 3;
            pbh[i] = *reinterpret_cast<const uint4*>(Bh + (size_t)(n0 + r) * K + k0 + gg * 8);
            pbl[i] = *reinterpret_cast<const uint4*>(Bl + (size_t)(n0 + r) * K + k0 + gg * 8);
        }
    }

    float acc[4][4][4] = {};   // [mt][nt][reg]

    for (int c = 0; c < nch; c++) {
        // ---- store prefetched chunk to smem (with fp32->bf16 hi/lo split for A)
        #pragma unroll
        for (int i = 0; i < 4; i++) {
            int id = tid + i * 256;
            int r = id >> 3, c4 = id & 7;
            float vx = pa[i].x, vy = pa[i].y, vz = pa[i].z, vw = pa[i].w;
            __nv_bfloat162 h0 = __floats2bfloat162_rn(vx, vy);
            __nv_bfloat162 h1 = __floats2bfloat162_rn(vz, vw);
            float2 hf0 = __bfloat1622float2(h0);
            float2 hf1 = __bfloat1622float2(h1);
            __nv_bfloat162 l0 = __floats2bfloat162_rn(vx - hf0.x, vy - hf0.y);
            __nv_bfloat162 l1 = __floats2bfloat162_rn(vz - hf1.x, vw - hf1.y);
            int w = r * GROW + c4 * 2;
            sAh[w]     = *reinterpret_cast<uint32_t*>(&h0);
            sAh[w + 1] = *reinterpret_cast<uint32_t*>(&h1);
            sAl[w]     = *reinterpret_cast<uint32_t*>(&l0);
            sAl[w + 1] = *reinterpret_cast<uint32_t*>(&l1);
        }
        #pragma unroll
        for (int i = 0; i < 2; i++) {
            int id = tid + i * 256;
            int r = id >> 2, gg = id & 3;
            *reinterpret_cast<uint4*>(&sBh[r * GROW + gg * 4]) = pbh[i];
            *reinterpret_cast<uint4*>(&sBl[r * GROW + gg * 4]) = pbl[i];
        }
        __syncthreads();

        // ---- prefetch next chunk (overlaps with mma below)
        if (c + 1 < nch) {
            const int k0 = (c + 1) << 5;
            #pragma unroll
            for (int i = 0; i < 4; i++) {
                int id = tid + i * 256;
                int r = id >> 3, c4 = id & 7;
                pa[i] = *reinterpret_cast<const float4*>(A + (size_t)(m0 + r) * K + k0 + c4 * 4);
            }
            #pragma unroll
            for (int i = 0; i < 2; i++) {
                int id = tid + i * 256;
                int r = id >> 2, gg = id & 3;
                pbh[i] = *reinterpret_cast<const uint4*>(Bh + (size_t)(n0 + r) * K + k0 + gg * 8);
                pbl[i] = *reinterpret_cast<const uint4*>(Bl + (size_t)(n0 + r) * K + k0 + gg * 8);
            }
        }

        // ---- mma over this chunk: 2 k16 steps
        #pragma unroll
        for (int ks = 0; ks < 2; ks++) {
            uint32_t ah[4][4], al[4][4];
            #pragma unroll
            for (int mt = 0; mt < 4; mt++) {
                int w0 = (wm + mt * 16 + g) * GROW + ks * 8 + tg;
                ah[mt][0] = sAh[w0];
                ah[mt][1] = sAh[w0 + 8 * GROW];
                ah[mt][2] = sAh[w0 + 4];
                ah[mt][3] = sAh[w0 + 8 * GROW + 4];
                al[mt][0] = sAl[w0];
                al[mt][1] = sAl[w0 + 8 * GROW];
                al[mt][2] = sAl[w0 + 4];
                al[mt][3] = sAl[w0 + 8 * GROW + 4];
            }
            #pragma unroll
            for (int nt = 0; nt < 4; nt++) {
                int w0 = (wn + nt * 8 + g) * GROW + ks * 8 + tg;
                uint32_t bh0 = sBh[w0], bh1 = sBh[w0 + 4];
                uint32_t bl0 = sBl[w0], bl1 = sBl[w0 + 4];
                #pragma unroll
                for (int mt = 0; mt < 4; mt++) {
                    MMA_BF16(acc[mt][nt], ah[mt], bh0, bh1);
                    MMA_BF16(acc[mt][nt], ah[mt], bl0, bl1);
                    MMA_BF16(acc[mt][nt], al[mt], bh0, bh1);
                }
            }
        }
        __syncthreads();
    }

    // ---- epilogue: fragment layout c0..c3 -> C
    #pragma unroll
    for (int mt = 0; mt < 4; mt++) {
        const int r = m0 + wm + mt * 16 + g;
        #pragma unroll
        for (int nt = 0; nt < 4; nt++) {
            const int cc = n0 + wn + nt * 8 + tg * 2;
            float2 v0 = make_float2(acc[mt][nt][0], acc[mt][nt][1]);
            float2 v1 = make_float2(acc[mt][nt][2], acc[mt][nt][3]);
            if (bias) {
                float b0 = bias[cc], b1 = bias[cc + 1];
                v0.x += b0; v0.y += b1;
                v1.x += b0; v1.y += b1;
            }
            *reinterpret_cast<float2*>(C + (size_t)r * N + cc)       = v0;
            *reinterpret_cast<float2*>(C + (size_t)(r + 8) * N + cc) = v1;
        }
    }
}

// ---------------------------------------------------------------------------
// Fused flash attention, fp32 SIMT, FMA-exp, vectorized smem.
// 128 q x 128 kv tiles, 256 threads (16x16): QK micro 8keys x 8q (S^T),
// PV micro 8q x 4d. Transposed smem layouts for float4 operand loads.
// ---------------------------------------------------------------------------
__device__ __forceinline__ float fast_exp(float x) {
    x = fmaxf(x, -80.0f);
    float y = x * 1.4426950408889634f;   // log2(e)
    float n = rintf(y);
    float f = y - n;
    float p = 1.3333558146e-3f;          // ln2^5/5!
    p = fmaf(p, f, 9.6181291076e-3f);    // ln2^4/4!
    p = fmaf(p, f, 5.5504108665e-2f);    // ln2^3/3!
    p = fmaf(p, f, 2.4022650696e-1f);    // ln2^2/2!
    p = fmaf(p, f, 6.9314718056e-1f);    // ln2
    p = fmaf(p, f, 1.0f);
    return p * __int_as_float(((int)n + 127) << 23);
}

#define QT_STRIDE 132
#define VS_STRIDE 68
#define AT_QT_OFF 0
#define AT_KV_OFF 8448                   // 64*132
#define AT_PT_OFF 17152                  // + max(64*132, 128*68)=8704
#define AT_SMEM_FLOATS (AT_PT_OFF + 128 * 128)
#define AT_SMEM_BYTES  (AT_SMEM_FLOATS * 4)

__global__ __launch_bounds__(256, 1) void attn_kernel(
    const float* __restrict__ Q, const float* __restrict__ Kg,
    const float* __restrict__ Vg, float* __restrict__ AO)
{
    extern __shared__ float sf[];
    float* Qt = sf + AT_QT_OFF;          // [64][132]  (d-major)
    float* KV = sf + AT_KV_OFF;          // Kt [64][132] / Vs [128][68]
    float* Pt = sf + AT_PT_OFF;          // [128][128], 16B-granule XOR swizzle

    const int tid = threadIdx.x;
    const int tx = tid & 15, ty = tid >> 4;
    const int r0 = ty * 8;               // q block of this thread
    const int c0 = tx * 8;               // key block of this thread (QK)

    const int q0 = blockIdx.x * 128;
    const int bh = blockIdx.y, b = bh >> 3, h = bh & 7;

    const float* Qp = Q  + ((size_t)(b * NQ)  + q0) * INNER + h * DHEAD;
    const float* Kp = Kg +  (size_t)(b * NKK)       * INNER + h * DHEAD;
    const float* Vp = Vg +  (size_t)(b * NKK)       * INNER + h * DHEAD;

    // Load Q transposed: Qt[d][q]
    {
        const int qi = tid & 127, half = tid >> 7;
        const float* src = Qp + (size_t)qi * INNER + half * 32;
        #pragma unroll
        for (int j = 0; j < 8; j++) {
            float4 v = *reinterpret_cast<const float4*>(src + j * 4);
            int d = half * 32 + j * 4;
            Qt[(d + 0) * QT_STRIDE + qi] = v.x;
            Qt[(d + 1) * QT_STRIDE + qi] = v.y;
            Qt[(d + 2) * QT_STRIDE + qi] = v.z;
            Qt[(d + 3) * QT_STRIDE + qi] = v.w;
        }
    }

    float m_run[8], l_run[8];
    float oacc[8][4] = {};
    #pragma unroll
    for (int i = 0; i < 8; i++) { m_run[i] = -1e30f; l_run[i] = 0.0f; }
    __syncthreads();

    for (int kt = 0; kt < NKK / 128; kt++) {
        // Load K transposed: Kt[d][key]
        {
            const int ki = tid & 127, half = tid >> 7;
            const float* src = Kp + (size_t)(kt * 128 + ki) * INNER + half * 32;
            #pragma unroll
            for (int j = 0; j < 8; j++) {
                float4 v = *reinterpret_cast<const float4*>(src + j * 4);
                int d = half * 32 + j * 4;
                KV[(d + 0) * QT_STRIDE + ki] = v.x;
                KV[(d + 1) * QT_STRIDE + ki] = v.y;
                KV[(d + 2) * QT_STRIDE + ki] = v.z;
                KV[(d + 3) * QT_STRIDE + ki] = v.w;
            }
        }
        __syncthreads();

        // S^T micro-tile: st[key j][q i]
        float st[8][8] = {};
        #pragma unroll 4
        for (int d = 0; d < 64; d++) {
            const float4* kr = reinterpret_cast<const float4*>(KV + d * QT_STRIDE);
            const float4* qr = reinterpret_cast<const float4*>(Qt + d * QT_STRIDE);
            float4 ka = kr[tx * 2], kb = kr[tx * 2 + 1];
            float4 qa = qr[ty * 2], qb = qr[ty * 2 + 1];
            float kv8[8] = {ka.x, ka.y, ka.z, ka.w, kb.x, kb.y, kb.z, kb.w};
            float qv8[8] = {qa.x, qa.y, qa.z, qa.w, qb.x, qb.y, qb.z, qb.w};
            #pragma unroll
            for (int j = 0; j < 8; j++)
                #pragma unroll
                for (int i = 0; i < 8; i++)
                    st[j][i] = fmaf(kv8[j], qv8[i], st[j][i]);
        }
        #pragma unroll
        for (int j = 0; j < 8; j++)
            #pragma unroll
            for (int i = 0; i < 8; i++)
                st[j][i] *= 0.125f;      // scale = DIM_HEAD^-0.5

        // Online softmax (per q row i, reduced across the 16 tx lanes)
        #pragma unroll
        for (int i = 0; i < 8; i++) {
            float vmax = st[0][i];
            #pragma unroll
            for (int j = 1; j < 8; j++) vmax = fmaxf(vmax, st[j][i]);
            #pragma unroll
            for (int off = 8; off >= 1; off >>= 1)
                vmax = fmaxf(vmax, __shfl_xor_sync(0xffffffffu, vmax, off));
            float mnew = fmaxf(m_run[i], vmax);
            float rsc = fast_exp(m_run[i] - mnew);
            m_run[i] = mnew;
            float s = 0.0f;
            #pragma unroll
            for (int j = 0; j < 8; j++) {
                float p = fast_exp(st[j][i] - mnew);
                st[j][i] = p;
                s += p;
            }
            #pragma unroll
            for (int off = 8; off >= 1; off >>= 1)
                s += __shfl_xor_sync(0xffffffffu, s, off);
            l_run[i] = l_run[i] * rsc + s;
            #pragma unroll
            for (int jd = 0; jd < 4; jd++) oacc[i][jd] *= rsc;
        }

        // Write P^T to Pt with 16B-granule XOR swizzle
        #pragma unroll
        for (int j = 0; j < 8; j++) {
            const int key = c0 + j;
            const int s3 = (key >> 3) & 7;
            float* prow = Pt + key * 128;
            #pragma unroll
            for (int i4 = 0; i4 < 2; i4++) {
                float4 v = make_float4(st[j][i4 * 4 + 0], st[j][i4 * 4 + 1],
                                       st[j][i4 * 4 + 2], st[j][i4 * 4 + 3]);
                *reinterpret_cast<float4*>(prow + (((ty * 2 + i4) ^ s3) << 2)) = v;
            }
        }
        __syncthreads();                 // Kt reads done; Pt visible

        // Load V natural: Vs[key][d]
        {
            const int ki = tid >> 1, half = tid & 1;
            const float* src = Vp + (size_t)(kt * 128 + ki) * INNER + half * 32;
            float* dst = KV + ki * VS_STRIDE + half * 32;
            #pragma unroll
            for (int j = 0; j < 8; j++)
                *reinterpret_cast<float4*>(dst + j * 4) =
                    *reinterpret_cast<const float4*>(src + j * 4);
        }
        __syncthreads();                 // Vs ready

        // O[q][d] += P^T[key][q] * V[key][d]; thread: q r0..r0+7, d tx*4..+4
        #pragma unroll 4
        for (int key = 0; key < 128; key++) {
            const int s3 = (key >> 3) & 7;
            const float* prow = Pt + key * 128;
            float4 a0 = *reinterpret_cast<const float4*>(prow + (((ty * 2 + 0) ^ s3) << 2));
            float4 a1 = *reinterpret_cast<const float4*>(prow + (((ty * 2 + 1) ^ s3) << 2));
            float4 bv = *reinterpret_cast<const float4*>(KV + key * VS_STRIDE + tx * 4);
            float av[8] = {a0.x, a0.y, a0.z, a0.w, a1.x, a1.y, a1.z, a1.w};
            float bb[4] = {bv.x, bv.y, bv.z, bv.w};
            #pragma unroll
            for (int i = 0; i < 8; i++)
                #pragma unroll
                for (int jd = 0; jd < 4; jd++)
                    oacc[i][jd] = fmaf(av[i], bb[jd], oacc[i][jd]);
        }
        __syncthreads();                 // Vs/Pt free for next tile
    }

    // Epilogue: normalize, store
    #pragma unroll
    for (int i = 0; i < 8; i++) {
        float inv = 1.0f / l_run[i];
        float4 v = make_float4(oacc[i][0] * inv, oacc[i][1] * inv,
                               oacc[i][2] * inv, oacc[i][3] * inv);
        *reinterpret_cast<float4*>(
            AO + ((size_t)(b * NQ) + q0 + r0 + i) * INNER + h * DHEAD + tx * 4) = v;
    }
}

// ---------------------------------------------------------------------------
// Launcher
// ---------------------------------------------------------------------------
extern "C" void kernel_launch(void* const* d_in, const int* in_sizes, int n_in,
                              void* d_out, int out_size)
{
    const float* x   = (const float*)d_in[0];  // [4,2048,512]
    const float* ctx = (const float*)d_in[1];  // [4,1024,768]
    const float* Wq  = (const float*)d_in[2];  // [512,512]
    const float* Wk  = (const float*)d_in[3];  // [768,512]
    const float* Wv  = (const float*)d_in[4];  // [768,512]
    const float* Wo  = (const float*)d_in[5];  // [512,512]
    const float* bo  = (const float*)d_in[6];  // [512]
    float* out = (float*)d_out;

    float *Qb, *Kb, *Vb, *AOb;
    cudaGetSymbolAddress((void**)&Qb,  g_Q);
    cudaGetSymbolAddress((void**)&Kb,  g_K);
    cudaGetSymbolAddress((void**)&Vb,  g_V);
    cudaGetSymbolAddress((void**)&AOb, g_AO);

    __nv_bfloat16 *WqTh, *WqTl, *WkTh, *WkTl, *WvTh, *WvTl, *WoTh, *WoTl;
    cudaGetSymbolAddress((void**)&WqTh, g_WqTh); cudaGetSymbolAddress((void**)&WqTl, g_WqTl);
    cudaGetSymbolAddress((void**)&WkTh, g_WkTh); cudaGetSymbolAddress((void**)&WkTl, g_WkTl);
    cudaGetSymbolAddress((void**)&WvTh, g_WvTh); cudaGetSymbolAddress((void**)&WvTl, g_WvTl);
    cudaGetSymbolAddress((void**)&WoTh, g_WoTh); cudaGetSymbolAddress((void**)&WoTl, g_WoTl);

    cudaFuncSetAttribute(attn_kernel,
                         cudaFuncAttributeMaxDynamicSharedMemorySize, AT_SMEM_BYTES);

    // --- weight transpose + hi/lo split ---
    splitT_kernel<<<dim3(INNER / 32, DQ / 32), dim3(32, 8)>>>(Wq, WqTh, WqTl, DQ, INNER);
    splitT_kernel<<<dim3(INNER / 32, DC / 32), dim3(32, 8)>>>(Wk, WkTh, WkTl, DC, INNER);
    splitT_kernel<<<dim3(INNER / 32, DC / 32), dim3(32, 8)>>>(Wv, WvTh, WvTl, DC, INNER);
    splitT_kernel<<<dim3(DQ / 32, INNER / 32), dim3(32, 8)>>>(Wo, WoTh, WoTl, INNER, DQ);

    // --- projections on HMMA tensor cores (A split in-kernel) ---
    hgemm_kernel<<<dim3(INNER / 128, (NB * NQ) / 128), 256>>>(
        x, WqTh, WqTl, nullptr, Qb, NB * NQ, DQ, INNER);
    hgemm_kernel<<<dim3(INNER / 128, (NB * NKK) / 128), 256>>>(
        ctx, WkTh, WkTl, nullptr, Kb, NB * NKK, DC, INNER);
    hgemm_kernel<<<dim3(INNER / 128, (NB * NKK) / 128), 256>>>(
        ctx, WvTh, WvTl, nullptr, Vb, NB * NKK, DC, INNER);

    // --- fused attention ---
    attn_kernel<<<dim3(NQ / 128, NB * NHEAD), 256, AT_SMEM_BYTES>>>(Qb, Kb, Vb, AOb);

    // --- output projection (+bias) ---
    hgemm_kernel<<<dim3(DQ / 128, (NB * NQ) / 128), 256>>>(
        AOb, WoTh, WoTl, bo, out, NB * NQ, INNER, DQ);
}

// round 7
// speedup vs baseline: 3.1286x; 1.8310x over previous
#include <cuda_runtime.h>
#include <cuda_bf16.h>
#include <cstdint>
#include <cstddef>

// Problem constants
#define NB    4
#define NQ    2048
#define DQ    512
#define NKK   1024
#define DC    768
#define NHEAD 8
#define DHEAD 64
#define INNER 512   // NHEAD*DHEAD

// ---------------------------------------------------------------------------
// Scratch (device globals — no allocation allowed)
// ---------------------------------------------------------------------------
__device__ float g_AO[NB * NQ  * INNER];

// split activations produced by projection GEMM epilogues
__device__ __nv_bfloat16 g_Qh [NB * NQ  * INNER], g_Ql [NB * NQ  * INNER];
__device__ __nv_bfloat16 g_Kh [NB * NKK * INNER], g_Kl [NB * NKK * INNER];
__device__ __nv_bfloat16 g_Vth[NB * INNER * NKK], g_Vtl[NB * INNER * NKK]; // [b][hd][key]

// transposed + split weights: WT[n][k] = W[k][n]
__device__ __nv_bfloat16 g_WqTh[INNER * DQ],  g_WqTl[INNER * DQ];
__device__ __nv_bfloat16 g_WkTh[INNER * DC],  g_WkTl[INNER * DC];
__device__ __nv_bfloat16 g_WvTh[INNER * DC],  g_WvTl[INNER * DC];
__device__ __nv_bfloat16 g_WoTh[DQ * INNER],  g_WoTl[DQ * INNER];

// ---------------------------------------------------------------------------
// Transpose + split: W[K][N] -> WT hi/lo [N][K], with optional scale
// ---------------------------------------------------------------------------
__global__ void splitT_kernel(const float* __restrict__ W,
                              __nv_bfloat16* __restrict__ hT,
                              __nv_bfloat16* __restrict__ lT,
                              int K, int N, float scale)
{
    __shared__ float t[32][33];
    const int n0 = blockIdx.x * 32, k0 = blockIdx.y * 32;
    const int tx = threadIdx.x, ty = threadIdx.y;
    #pragma unroll
    for (int r = ty; r < 32; r += 8)
        t[r][tx] = W[(size_t)(k0 + r) * N + n0 + tx];
    __syncthreads();
    #pragma unroll
    for (int r = ty; r < 32; r += 8) {
        float v = t[tx][r] * scale;       // element (n = n0+r, k = k0+tx)
        __nv_bfloat16 h = __float2bfloat16(v);
        size_t idx = (size_t)(n0 + r) * K + k0 + tx;
        hT[idx] = h;
        lT[idx] = __float2bfloat16(v - __bfloat162float(h));
    }
}

// ---------------------------------------------------------------------------
// HMMA bf16-split GEMM: C = A[M,K](fp32, split in-kernel) @ B^T (B=[N,K] split).
// 128x128 CTA tile, BK=32, 8 warps (2m x 4n), warp tile 64x32, m16n8k16.
// Epilogue MODE: 0 = fp32 C (+bias); 1 = split bf16 natural (Ch/Cl);
//                2 = split bf16 transposed-for-V (Vt[b][col][key]).
// ---------------------------------------------------------------------------
#define GROW 20   // words per smem row (40 bf16 = 80B)

#define MMA_BF16(d, a, b0, b1) \
    asm volatile("mma.sync.aligned.m16n8k16.row.col.f32.bf16.bf16.f32 " \
        "{%0,%1,%2,%3}, {%4,%5,%6,%7}, {%8,%9}, {%0,%1,%2,%3};" \
        : "+f"((d)[0]), "+f"((d)[1]), "+f"((d)[2]), "+f"((d)[3]) \
        : "r"((a)[0]), "r"((a)[1]), "r"((a)[2]), "r"((a)[3]), \
          "r"(b0), "r"(b1))

template <int MODE>
__global__ __launch_bounds__(256, 1) void hgemm_kernel(
    const float* __restrict__ A,
    const __nv_bfloat16* __restrict__ Bh, const __nv_bfloat16* __restrict__ Bl,
    const float* __restrict__ bias, float* __restrict__ C,
    __nv_bfloat16* __restrict__ Ch, __nv_bfloat16* __restrict__ Cl,
    int M, int K, int N)
{
    __shared__ __align__(16) uint32_t sAh[128 * GROW];
    __shared__ __align__(16) uint32_t sAl[128 * GROW];
    __shared__ __align__(16) uint32_t sBh[128 * GROW];
    __shared__ __align__(16) uint32_t sBl[128 * GROW];

    const int tid  = threadIdx.x;
    const int lane = tid & 31, wid = tid >> 5;
    const int wm = (wid >> 2) * 64;     // warp m base: 0 or 64
    const int wn = (wid & 3) * 32;      // warp n base: 0..96
    const int g  = lane >> 2, tg = lane & 3;
    const int m0 = blockIdx.y * 128, n0 = blockIdx.x * 128;

    const int nch = K >> 5;

    float4 pa[4];
    uint4  pbh[2], pbl[2];

    // prefetch chunk 0
    {
        #pragma unroll
        for (int i = 0; i < 4; i++) {
            int id = tid + i * 256;
            int r = id >> 3, c4 = id & 7;
            pa[i] = *reinterpret_cast<const float4*>(A + (size_t)(m0 + r) * K + c4 * 4);
        }
        #pragma unroll
        for (int i = 0; i < 2; i++) {
            int id = tid + i * 256;
            int r = id >> 2, gg = id & 3;
            pbh[i] = *reinterpret_cast<const uint4*>(Bh + (size_t)(n0 + r) * K + gg * 8);
            pbl[i] = *reinterpret_cast<const uint4*>(Bl + (size_t)(n0 + r) * K + gg * 8);
        }
    }

    float acc[4][4][4] = {};   // [mt][nt][reg]

    for (int c = 0; c < nch; c++) {
        // ---- store prefetched chunk to smem (fp32->bf16 hi/lo split for A)
        #pragma unroll
        for (int i = 0; i < 4; i++) {
            int id = tid + i * 256;
            int r = id >> 3, c4 = id & 7;
            float vx = pa[i].x, vy = pa[i].y, vz = pa[i].z, vw = pa[i].w;
            __nv_bfloat162 h0 = __floats2bfloat162_rn(vx, vy);
            __nv_bfloat162 h1 = __floats2bfloat162_rn(vz, vw);
            float2 hf0 = __bfloat1622float2(h0);
            float2 hf1 = __bfloat1622float2(h1);
            __nv_bfloat162 l0 = __floats2bfloat162_rn(vx - hf0.x, vy - hf0.y);
            __nv_bfloat162 l1 = __floats2bfloat162_rn(vz - hf1.x, vw - hf1.y);
            int w = r * GROW + c4 * 2;
            sAh[w]     = *reinterpret_cast<uint32_t*>(&h0);
            sAh[w + 1] = *reinterpret_cast<uint32_t*>(&h1);
            sAl[w]     = *reinterpret_cast<uint32_t*>(&l0);
            sAl[w + 1] = *reinterpret_cast<uint32_t*>(&l1);
        }
        #pragma unroll
        for (int i = 0; i < 2; i++) {
            int id = tid + i * 256;
            int r = id >> 2, gg = id & 3;
            *reinterpret_cast<uint4*>(&sBh[r * GROW + gg * 4]) = pbh[i];
            *reinterpret_cast<uint4*>(&sBl[r * GROW + gg * 4]) = pbl[i];
        }
        __syncthreads();

        // ---- prefetch next chunk (overlaps with mma below)
        if (c + 1 < nch) {
            const int k0 = (c + 1) << 5;
            #pragma unroll
            for (int i = 0; i < 4; i++) {
                int id = tid + i * 256;
                int r = id >> 3, c4 = id & 7;
                pa[i] = *reinterpret_cast<const float4*>(A + (size_t)(m0 + r) * K + k0 + c4 * 4);
            }
            #pragma unroll
            for (int i = 0; i < 2; i++) {
                int id = tid + i * 256;
                int r = id >> 2, gg = id & 3;
                pbh[i] = *reinterpret_cast<const uint4*>(Bh + (size_t)(n0 + r) * K + k0 + gg * 8);
                pbl[i] = *reinterpret_cast<const uint4*>(Bl + (size_t)(n0 + r) * K + k0 + gg * 8);
            }
        }

        // ---- mma over this chunk: 2 k16 steps
        #pragma unroll
        for (int ks = 0; ks < 2; ks++) {
            uint32_t ah[4][4], al[4][4];
            #pragma unroll
            for (int mt = 0; mt < 4; mt++) {
                int w0 = (wm + mt * 16 + g) * GROW + ks * 8 + tg;
                ah[mt][0] = sAh[w0];
                ah[mt][1] = sAh[w0 + 8 * GROW];
                ah[mt][2] = sAh[w0 + 4];
                ah[mt][3] = sAh[w0 + 8 * GROW + 4];
                al[mt][0] = sAl[w0];
                al[mt][1] = sAl[w0 + 8 * GROW];
                al[mt][2] = sAl[w0 + 4];
                al[mt][3] = sAl[w0 + 8 * GROW + 4];
            }
            #pragma unroll
            for (int nt = 0; nt < 4; nt++) {
                int w0 = (wn + nt * 8 + g) * GROW + ks * 8 + tg;
                uint32_t bh0 = sBh[w0], bh1 = sBh[w0 + 4];
                uint32_t bl0 = sBl[w0], bl1 = sBl[w0 + 4];
                #pragma unroll
                for (int mt = 0; mt < 4; mt++) {
                    MMA_BF16(acc[mt][nt], ah[mt], bh0, bh1);
                    MMA_BF16(acc[mt][nt], ah[mt], bl0, bl1);
                    MMA_BF16(acc[mt][nt], al[mt], bh0, bh1);
                }
            }
        }
        __syncthreads();
    }

    // ---- epilogue
    #pragma unroll
    for (int mt = 0; mt < 4; mt++) {
        const int r = m0 + wm + mt * 16 + g;
        #pragma unroll
        for (int nt = 0; nt < 4; nt++) {
            const int cc = n0 + wn + nt * 8 + tg * 2;
            if (MODE == 0) {
                float2 v0 = make_float2(acc[mt][nt][0], acc[mt][nt][1]);
                float2 v1 = make_float2(acc[mt][nt][2], acc[mt][nt][3]);
                if (bias) {
                    float b0 = bias[cc], b1 = bias[cc + 1];
                    v0.x += b0; v0.y += b1;
                    v1.x += b0; v1.y += b1;
                }
                *reinterpret_cast<float2*>(C + (size_t)r * N + cc)       = v0;
                *reinterpret_cast<float2*>(C + (size_t)(r + 8) * N + cc) = v1;
            } else if (MODE == 1) {
                #pragma unroll
                for (int rr = 0; rr < 2; rr++) {
                    float v0 = acc[mt][nt][rr * 2], v1 = acc[mt][nt][rr * 2 + 1];
                    __nv_bfloat162 h = __floats2bfloat162_rn(v0, v1);
                    float2 hf = __bfloat1622float2(h);
                    __nv_bfloat162 l = __floats2bfloat162_rn(v0 - hf.x, v1 - hf.y);
                    size_t idx = (size_t)(r + rr * 8) * N + cc;
                    *reinterpret_cast<uint32_t*>(Ch + idx) = *reinterpret_cast<uint32_t*>(&h);
                    *reinterpret_cast<uint32_t*>(Cl + idx) = *reinterpret_cast<uint32_t*>(&l);
                }
            } else {   // MODE 2: V transposed split  Vt[b][col][key]
                #pragma unroll
                for (int rr = 0; rr < 2; rr++) {
                    int rg = r + rr * 8;
                    int bb = rg >> 10, key = rg & (NKK - 1);
                    #pragma unroll
                    for (int jc = 0; jc < 2; jc++) {
                        float v = acc[mt][nt][rr * 2 + jc];
                        __nv_bfloat16 h = __float2bfloat16(v);
                        size_t idx = ((size_t)bb * INNER + cc + jc) * NKK + key;
                        Ch[idx] = h;
                        Cl[idx] = __float2bfloat16(v - __bfloat162float(h));
                    }
                }
            }
        }
    }
}

// ---------------------------------------------------------------------------
// HMMA flash attention. CTA = 128 q x one (b,h); 8 warps, warp = 16 q rows.
// kv tiles of 128. Q/K/V pre-split bf16 (scale folded into Wq).
// S in fp32 accum regs -> register softmax -> P split in regs -> PV on HMMA.
// ---------------------------------------------------------------------------
__device__ __forceinline__ float fast_exp(float x) {
    x = fmaxf(x, -80.0f);
    float y = x * 1.4426950408889634f;   // log2(e)
    float n = rintf(y);
    float f = y - n;
    float p = 1.3333558146e-3f;
    p = fmaf(p, f, 9.6181291076e-3f);
    p = fmaf(p, f, 5.5504108665e-2f);
    p = fmaf(p, f, 2.4022650696e-1f);
    p = fmaf(p, f, 6.9314718056e-1f);
    p = fmaf(p, f, 1.0f);
    return p * __int_as_float(((int)n + 127) << 23);
}

// smem word offsets (uint32 words)
#define AQ_H 0
#define AQ_L 4608        // 128*36
#define AK_H 9216
#define AK_L 13824
#define AV_H 18432       // Vt: 64 rows x 68 words
#define AV_L 22784
#define ATT_WORDS 27136
#define ATT_BYTES (ATT_WORDS * 4)

__global__ __launch_bounds__(256, 1) void attn_mma_kernel(
    const __nv_bfloat16* __restrict__ Qh_, const __nv_bfloat16* __restrict__ Ql_,
    const __nv_bfloat16* __restrict__ Kh_, const __nv_bfloat16* __restrict__ Kl_,
    const __nv_bfloat16* __restrict__ Vh_, const __nv_bfloat16* __restrict__ Vl_,
    float* __restrict__ AO)
{
    extern __shared__ uint32_t sw[];
    const int tid = threadIdx.x, lane = tid & 31, w = tid >> 5;
    const int g = lane >> 2, tg = lane & 3;
    const int q0 = blockIdx.x * 128;
    const int bh = blockIdx.y, b = bh >> 3, h = bh & 7;

    // ---- load Q tile [128 q][64 d] hi/lo
    {
        const __nv_bfloat16* sh = Qh_ + ((size_t)(b * NQ + q0)) * INNER + h * 64;
        const __nv_bfloat16* sl = Ql_ + ((size_t)(b * NQ + q0)) * INNER + h * 64;
        #pragma unroll
        for (int i = 0; i < 4; i++) {
            int id = tid + i * 256;
            int r = id >> 3, u = id & 7;
            uint4 vh = *reinterpret_cast<const uint4*>(sh + (size_t)r * INNER + u * 8);
            uint4 vl = *reinterpret_cast<const uint4*>(sl + (size_t)r * INNER + u * 8);
            *reinterpret_cast<uint4*>(&sw[AQ_H + r * 36 + u * 4]) = vh;
            *reinterpret_cast<uint4*>(&sw[AQ_L + r * 36 + u * 4]) = vl;
        }
    }

    float o[8][4] = {};
    float m0 = -1e30f, m1 = -1e30f, l0 = 0.0f, l1 = 0.0f;

    for (int kt = 0; kt < NKK / 128; kt++) {
        if (kt) __syncthreads();         // prior tile's smem reads done

        // ---- load K tile [128 key][64 d] hi/lo
        {
            const __nv_bfloat16* sh = Kh_ + ((size_t)(b * NKK + kt * 128)) * INNER + h * 64;
            const __nv_bfloat16* sl = Kl_ + ((size_t)(b * NKK + kt * 128)) * INNER + h * 64;
            #pragma unroll
            for (int i = 0; i < 4; i++) {
                int id = tid + i * 256;
                int r = id >> 3, u = id & 7;
                uint4 vh = *reinterpret_cast<const uint4*>(sh + (size_t)r * INNER + u * 8);
                uint4 vl = *reinterpret_cast<const uint4*>(sl + (size_t)r * INNER + u * 8);
                *reinterpret_cast<uint4*>(&sw[AK_H + r * 36 + u * 4]) = vh;
                *reinterpret_cast<uint4*>(&sw[AK_L + r * 36 + u * 4]) = vl;
            }
        }
        // ---- load Vt tile [64 d][128 key] hi/lo
        {
            const __nv_bfloat16* sh = Vh_ + ((size_t)(b * INNER + h * 64)) * NKK + kt * 128;
            const __nv_bfloat16* sl = Vl_ + ((size_t)(b * INNER + h * 64)) * NKK + kt * 128;
            #pragma unroll
            for (int i = 0; i < 4; i++) {
                int id = tid + i * 256;
                int r = id >> 4, u = id & 15;
                uint4 vh = *reinterpret_cast<const uint4*>(sh + (size_t)r * NKK + u * 8);
                uint4 vl = *reinterpret_cast<const uint4*>(sl + (size_t)r * NKK + u * 8);
                *reinterpret_cast<uint4*>(&sw[AV_H + r * 68 + u * 4]) = vh;
                *reinterpret_cast<uint4*>(&sw[AV_L + r * 68 + u * 4]) = vl;
            }
        }
        __syncthreads();

        // ---- S = Q K^T (3-product split), warp: 16 q x 128 keys
        float acc[16][4] = {};
        #pragma unroll
        for (int ks = 0; ks < 4; ks++) {
            int wq = (w * 16 + g) * 36 + ks * 8 + tg;
            uint32_t qh[4] = { sw[AQ_H + wq], sw[AQ_H + wq + 8 * 36],
                               sw[AQ_H + wq + 4], sw[AQ_H + wq + 8 * 36 + 4] };
            uint32_t ql[4] = { sw[AQ_L + wq], sw[AQ_L + wq + 8 * 36],
                               sw[AQ_L + wq + 4], sw[AQ_L + wq + 8 * 36 + 4] };
            #pragma unroll
            for (int nt = 0; nt < 16; nt++) {
                int wk = (nt * 8 + g) * 36 + ks * 8 + tg;
                uint32_t bh0 = sw[AK_H + wk], bh1 = sw[AK_H + wk + 4];
                uint32_t bl0 = sw[AK_L + wk], bl1 = sw[AK_L + wk + 4];
                MMA_BF16(acc[nt], qh, bh0, bh1);
                MMA_BF16(acc[nt], qh, bl0, bl1);
                MMA_BF16(acc[nt], ql, bh0, bh1);
            }
        }

        // ---- register online softmax (rows g and g+8)
        float tm0 = -1e30f, tm1 = -1e30f;
        #pragma unroll
        for (int nt = 0; nt < 16; nt++) {
            tm0 = fmaxf(tm0, fmaxf(acc[nt][0], acc[nt][1]));
            tm1 = fmaxf(tm1, fmaxf(acc[nt][2], acc[nt][3]));
        }
        tm0 = fmaxf(tm0, __shfl_xor_sync(0xffffffffu, tm0, 1));
        tm0 = fmaxf(tm0, __shfl_xor_sync(0xffffffffu, tm0, 2));
        tm1 = fmaxf(tm1, __shfl_xor_sync(0xffffffffu, tm1, 1));
        tm1 = fmaxf(tm1, __shfl_xor_sync(0xffffffffu, tm1, 2));
        float mn0 = fmaxf(m0, tm0), mn1 = fmaxf(m1, tm1);
        float r0 = fast_exp(m0 - mn0), r1 = fast_exp(m1 - mn1);
        m0 = mn0; m1 = mn1;
        float s0 = 0.0f, s1 = 0.0f;
        #pragma unroll
        for (int nt = 0; nt < 16; nt++) {
            acc[nt][0] = fast_exp(acc[nt][0] - mn0); s0 += acc[nt][0];
            acc[nt][1] = fast_exp(acc[nt][1] - mn0); s0 += acc[nt][1];
            acc[nt][2] = fast_exp(acc[nt][2] - mn1); s1 += acc[nt][2];
            acc[nt][3] = fast_exp(acc[nt][3] - mn1); s1 += acc[nt][3];
        }
        s0 += __shfl_xor_sync(0xffffffffu, s0, 1);
        s0 += __shfl_xor_sync(0xffffffffu, s0, 2);
        s1 += __shfl_xor_sync(0xffffffffu, s1, 1);
        s1 += __shfl_xor_sync(0xffffffffu, s1, 2);
        l0 = l0 * r0 + s0;
        l1 = l1 * r1 + s1;
        #pragma unroll
        for (int nt = 0; nt < 8; nt++) {
            o[nt][0] *= r0; o[nt][1] *= r0;
            o[nt][2] *= r1; o[nt][3] *= r1;
        }

        // ---- O += P V (P split in regs; 3 products), warp: 16 q x 64 d
        #pragma unroll
        for (int ks = 0; ks < 8; ks++) {
            uint32_t ah[4], al[4];
            {
                float c0 = acc[2 * ks][0],     c1 = acc[2 * ks][1];
                float c2 = acc[2 * ks][2],     c3 = acc[2 * ks][3];
                float d0 = acc[2 * ks + 1][0], d1 = acc[2 * ks + 1][1];
                float d2 = acc[2 * ks + 1][2], d3 = acc[2 * ks + 1][3];
                __nv_bfloat162 t;
                float2 tf;
                t = __floats2bfloat162_rn(c0, c1); tf = __bfloat1622float2(t);
                ah[0] = *reinterpret_cast<uint32_t*>(&t);
                t = __floats2bfloat162_rn(c0 - tf.x, c1 - tf.y);
                al[0] = *reinterpret_cast<uint32_t*>(&t);
                t = __floats2bfloat162_rn(c2, c3); tf = __bfloat1622float2(t);
                ah[1] = *reinterpret_cast<uint32_t*>(&t);
                t = __floats2bfloat162_rn(c2 - tf.x, c3 - tf.y);
                al[1] = *reinterpret_cast<uint32_t*>(&t);
                t = __floats2bfloat162_rn(d0, d1); tf = __bfloat1622float2(t);
                ah[2] = *reinterpret_cast<uint32_t*>(&t);
                t = __floats2bfloat162_rn(d0 - tf.x, d1 - tf.y);
                al[2] = *reinterpret_cast<uint32_t*>(&t);
                t = __floats2bfloat162_rn(d2, d3); tf = __bfloat1622float2(t);
                ah[3] = *reinterpret_cast<uint32_t*>(&t);
                t = __floats2bfloat162_rn(d2 - tf.x, d3 - tf.y);
                al[3] = *reinterpret_cast<uint32_t*>(&t);
            }
            #pragma unroll
            for (int nt = 0; nt < 8; nt++) {
                int wv = (nt * 8 + g) * 68 + ks * 8 + tg;
                uint32_t bh0 = sw[AV_H + wv], bh1 = sw[AV_H + wv + 4];
                uint32_t bl0 = sw[AV_L + wv], bl1 = sw[AV_L + wv + 4];
                MMA_BF16(o[nt], ah, bh0, bh1);
                MMA_BF16(o[nt], ah, bl0, bl1);
                MMA_BF16(o[nt], al, bh0, bh1);
            }
        }
    }

    // ---- epilogue: normalize, store fp32 AO
    float i0 = 1.0f / l0, i1 = 1.0f / l1;
    const int rg = q0 + w * 16 + g;
    #pragma unroll
    for (int nt = 0; nt < 8; nt++) {
        const int col = h * 64 + nt * 8 + tg * 2;
        float2 v0 = make_float2(o[nt][0] * i0, o[nt][1] * i0);
        float2 v1 = make_float2(o[nt][2] * i1, o[nt][3] * i1);
        *reinterpret_cast<float2*>(AO + (size_t)(b * NQ + rg) * INNER + col)     = v0;
        *reinterpret_cast<float2*>(AO + (size_t)(b * NQ + rg + 8) * INNER + col) = v1;
    }
}

// ---------------------------------------------------------------------------
// Launcher
// ---------------------------------------------------------------------------
extern "C" void kernel_launch(void* const* d_in, const int* in_sizes, int n_in,
                              void* d_out, int out_size)
{
    const float* x   = (const float*)d_in[0];  // [4,2048,512]
    const float* ctx = (const float*)d_in[1];  // [4,1024,768]
    const float* Wq  = (const float*)d_in[2];  // [512,512]
    const float* Wk  = (const float*)d_in[3];  // [768,512]
    const float* Wv  = (const float*)d_in[4];  // [768,512]
    const float* Wo  = (const float*)d_in[5];  // [512,512]
    const float* bo  = (const float*)d_in[6];  // [512]
    float* out = (float*)d_out;

    float* AOb;
    cudaGetSymbolAddress((void**)&AOb, g_AO);

    __nv_bfloat16 *Qh, *Ql, *Kh, *Kl, *Vth, *Vtl;
    cudaGetSymbolAddress((void**)&Qh,  g_Qh);   cudaGetSymbolAddress((void**)&Ql,  g_Ql);
    cudaGetSymbolAddress((void**)&Kh,  g_Kh);   cudaGetSymbolAddress((void**)&Kl,  g_Kl);
    cudaGetSymbolAddress((void**)&Vth, g_Vth);  cudaGetSymbolAddress((void**)&Vtl, g_Vtl);

    __nv_bfloat16 *WqTh, *WqTl, *WkTh, *WkTl, *WvTh, *WvTl, *WoTh, *WoTl;
    cudaGetSymbolAddress((void**)&WqTh, g_WqTh); cudaGetSymbolAddress((void**)&WqTl, g_WqTl);
    cudaGetSymbolAddress((void**)&WkTh, g_WkTh); cudaGetSymbolAddress((void**)&WkTl, g_WkTl);
    cudaGetSymbolAddress((void**)&WvTh, g_WvTh); cudaGetSymbolAddress((void**)&WvTl, g_WvTl);
    cudaGetSymbolAddress((void**)&WoTh, g_WoTh); cudaGetSymbolAddress((void**)&WoTl, g_WoTl);

    cudaFuncSetAttribute(attn_mma_kernel,
                         cudaFuncAttributeMaxDynamicSharedMemorySize, ATT_BYTES);

    // --- weight transpose + hi/lo split (softmax scale folded into Wq) ---
    splitT_kernel<<<dim3(INNER / 32, DQ / 32), dim3(32, 8)>>>(Wq, WqTh, WqTl, DQ, INNER, 0.125f);
    splitT_kernel<<<dim3(INNER / 32, DC / 32), dim3(32, 8)>>>(Wk, WkTh, WkTl, DC, INNER, 1.0f);
    splitT_kernel<<<dim3(INNER / 32, DC / 32), dim3(32, 8)>>>(Wv, WvTh, WvTl, DC, INNER, 1.0f);
    splitT_kernel<<<dim3(DQ / 32, INNER / 32), dim3(32, 8)>>>(Wo, WoTh, WoTl, INNER, DQ, 1.0f);

    // --- projections (epilogues emit pre-split operands for attention) ---
    hgemm_kernel<1><<<dim3(INNER / 128, (NB * NQ) / 128), 256>>>(
        x, WqTh, WqTl, nullptr, nullptr, Qh, Ql, NB * NQ, DQ, INNER);
    hgemm_kernel<1><<<dim3(INNER / 128, (NB * NKK) / 128), 256>>>(
        ctx, WkTh, WkTl, nullptr, nullptr, Kh, Kl, NB * NKK, DC, INNER);
    hgemm_kernel<2><<<dim3(INNER / 128, (NB * NKK) / 128), 256>>>(
        ctx, WvTh, WvTl, nullptr, nullptr, Vth, Vtl, NB * NKK, DC, INNER);

    // --- fused attention on tensor cores ---
    attn_mma_kernel<<<dim3(NQ / 128, NB * NHEAD), 256, ATT_BYTES>>>(
        Qh, Ql, Kh, Kl, Vth, Vtl, AOb);

    // --- output projection (+bias) ---
    hgemm_kernel<0><<<dim3(DQ / 128, (NB * NQ) / 128), 256>>>(
        AOb, WoTh, WoTl, bo, out, nullptr, nullptr, NB * NQ, INNER, DQ);
}

// round 9
// speedup vs baseline: 3.6371x; 1.1626x over previous
#include <cuda_runtime.h>
#include <cuda_bf16.h>
#include <cuda_fp16.h>
#include <cstdint>
#include <cstddef>

// Problem constants
#define NB    4
#define NQ    2048
#define DQ    512
#define NKK   1024
#define DC    768
#define NHEAD 8
#define DHEAD 64
#define INNER 512   // NHEAD*DHEAD

// log2(e) * DIM_HEAD^-0.5  (folded into Wq so softmax runs in exp2 domain)
#define QSCALE 0.1803368801111204f

// ---------------------------------------------------------------------------
// Scratch (device globals — no allocation allowed)
// ---------------------------------------------------------------------------
__device__ float g_AO[NB * NQ  * INNER];

// attention operands produced by projection GEMM epilogues (fp16)
__device__ __half g_Qh [NB * NQ  * INNER];                          // single
__device__ __half g_Kh [NB * NKK * INNER], g_Kl [NB * NKK * INNER]; // hi/lo
__device__ __half g_Vth[NB * INNER * NKK], g_Vtl[NB * INNER * NKK]; // hi/lo, [b][hd][key]

// transposed + split weights (bf16, for projection GEMMs): WT[n][k] = W[k][n]
__device__ __nv_bfloat16 g_WqTh[INNER * DQ],  g_WqTl[INNER * DQ];
__device__ __nv_bfloat16 g_WkTh[INNER * DC],  g_WkTl[INNER * DC];
__device__ __nv_bfloat16 g_WvTh[INNER * DC],  g_WvTl[INNER * DC];
__device__ __nv_bfloat16 g_WoTh[DQ * INNER],  g_WoTl[DQ * INNER];

// ---------------------------------------------------------------------------
// Batched transpose + split for all 4 weights in one launch.
// Per weight: W[K][N] -> WT hi/lo [N][K] (bf16), with scale.
// ---------------------------------------------------------------------------
__device__ __forceinline__ void splitT_tile(
    const float* __restrict__ W, __nv_bfloat16* __restrict__ hT,
    __nv_bfloat16* __restrict__ lT, int K, int N, float scale,
    int n0, int k0, int tx, int ty, float (*t)[33])
{
    #pragma unroll
    for (int r = ty; r < 32; r += 8)
        t[r][tx] = W[(size_t)(k0 + r) * N + n0 + tx];
    __syncthreads();
    #pragma unroll
    for (int r = ty; r < 32; r += 8) {
        float v = t[tx][r] * scale;       // element (n = n0+r, k = k0+tx)
        __nv_bfloat16 h = __float2bfloat16(v);
        size_t idx = (size_t)(n0 + r) * K + k0 + tx;
        hT[idx] = h;
        lT[idx] = __float2bfloat16(v - __bfloat162float(h));
    }
}

__global__ void splitT_all_kernel(
    const float* __restrict__ Wq, const float* __restrict__ Wk,
    const float* __restrict__ Wv, const float* __restrict__ Wo,
    __nv_bfloat16* __restrict__ WqTh, __nv_bfloat16* __restrict__ WqTl,
    __nv_bfloat16* __restrict__ WkTh, __nv_bfloat16* __restrict__ WkTl,
    __nv_bfloat16* __restrict__ WvTh, __nv_bfloat16* __restrict__ WvTl,
    __nv_bfloat16* __restrict__ WoTh, __nv_bfloat16* __restrict__ WoTl)
{
    __shared__ float t[32][33];
    const int tx = threadIdx.x, ty = threadIdx.y;
    int id = blockIdx.x;
    // Wq: K=512,N=512 -> 16x16=256 blocks; Wk/Wv: K=768,N=512 -> 16x24=384 each;
    // Wo: K=512,N=512 -> 256 blocks. Total 1280.
    if (id < 256) {
        int n0 = (id & 15) * 32, k0 = (id >> 4) * 32;
        splitT_tile(Wq, WqTh, WqTl, DQ, INNER, QSCALE, n0, k0, tx, ty, t);
    } else if (id < 640) {
        id -= 256;
        int n0 = (id & 15) * 32, k0 = (id >> 4) * 32;
        splitT_tile(Wk, WkTh, WkTl, DC, INNER, 1.0f, n0, k0, tx, ty, t);
    } else if (id < 1024) {
        id -= 640;
        int n0 = (id & 15) * 32, k0 = (id >> 4) * 32;
        splitT_tile(Wv, WvTh, WvTl, DC, INNER, 1.0f, n0, k0, tx, ty, t);
    } else {
        id -= 1024;
        int n0 = (id & 15) * 32, k0 = (id >> 4) * 32;
        splitT_tile(Wo, WoTh, WoTl, INNER, DQ, 1.0f, n0, k0, tx, ty, t);
    }
}

// ---------------------------------------------------------------------------
// HMMA bf16-split GEMM: C = A[M,K](fp32, split in-kernel) @ B^T (B=[N,K] split).
// 128x128 CTA tile, BK=32, 8 warps (2m x 4n), warp tile 64x32, m16n8k16.
// Epilogue MODE: 0 = fp32 C (+bias); 1 = fp16 single (Q);
//                2 = fp16 hi/lo natural (K); 3 = fp16 hi/lo transposed-V.
// ---------------------------------------------------------------------------
#define GROW 20   // words per smem row (40 bf16 = 80B)

#define MMA_BF16(d, a, b0, b1) \
    asm volatile("mma.sync.aligned.m16n8k16.row.col.f32.bf16.bf16.f32 " \
        "{%0,%1,%2,%3}, {%4,%5,%6,%7}, {%8,%9}, {%0,%1,%2,%3};" \
        : "+f"((d)[0]), "+f"((d)[1]), "+f"((d)[2]), "+f"((d)[3]) \
        : "r"((a)[0]), "r"((a)[1]), "r"((a)[2]), "r"((a)[3]), \
          "r"(b0), "r"(b1))

#define MMA_F16(d, a, b0, b1) \
    asm volatile("mma.sync.aligned.m16n8k16.row.col.f32.f16.f16.f32 " \
        "{%0,%1,%2,%3}, {%4,%5,%6,%7}, {%8,%9}, {%0,%1,%2,%3};" \
        : "+f"((d)[0]), "+f"((d)[1]), "+f"((d)[2]), "+f"((d)[3]) \
        : "r"((a)[0]), "r"((a)[1]), "r"((a)[2]), "r"((a)[3]), \
          "r"(b0), "r"(b1))

template <int MODE>
__global__ __launch_bounds__(256, 1) void hgemm_kernel(
    const float* __restrict__ A,
    const __nv_bfloat16* __restrict__ Bh, const __nv_bfloat16* __restrict__ Bl,
    const float* __restrict__ bias, float* __restrict__ C,
    __half* __restrict__ Ch, __half* __restrict__ Cl,
    int M, int K, int N)
{
    __shared__ __align__(16) uint32_t sAh[128 * GROW];
    __shared__ __align__(16) uint32_t sAl[128 * GROW];
    __shared__ __align__(16) uint32_t sBh[128 * GROW];
    __shared__ __align__(16) uint32_t sBl[128 * GROW];

    const int tid  = threadIdx.x;
    const int lane = tid & 31, wid = tid >> 5;
    const int wm = (wid >> 2) * 64;     // warp m base: 0 or 64
    const int wn = (wid & 3) * 32;      // warp n base: 0..96
    const int g  = lane >> 2, tg = lane & 3;
    const int m0 = blockIdx.y * 128, n0 = blockIdx.x * 128;

    const int nch = K >> 5;

    float4 pa[4];
    uint4  pbh[2], pbl[2];

    // prefetch chunk 0
    {
        #pragma unroll
        for (int i = 0; i < 4; i++) {
            int id = tid + i * 256;
            int r = id >> 3, c4 = id & 7;
            pa[i] = *reinterpret_cast<const float4*>(A + (size_t)(m0 + r) * K + c4 * 4);
        }
        #pragma unroll
        for (int i = 0; i < 2; i++) {
            int id = tid + i * 256;
            int r = id >> 2, gg = id & 3;
            pbh[i] = *reinterpret_cast<const uint4*>(Bh + (size_t)(n0 + r) * K + gg * 8);
            pbl[i] = *reinterpret_cast<const uint4*>(Bl + (size_t)(n0 + r) * K + gg * 8);
        }
    }

    float acc[4][4][4] = {};   // [mt][nt][reg]

    for (int c = 0; c < nch; c++) {
        // ---- store prefetched chunk to smem (fp32->bf16 hi/lo split for A)
        #pragma unroll
        for (int i = 0; i < 4; i++) {
            int id = tid + i * 256;
            int r = id >> 3, c4 = id & 7;
            float vx = pa[i].x, vy = pa[i].y, vz = pa[i].z, vw = pa[i].w;
            __nv_bfloat162 h0 = __floats2bfloat162_rn(vx, vy);
            __nv_bfloat162 h1 = __floats2bfloat162_rn(vz, vw);
            float2 hf0 = __bfloat1622float2(h0);
            float2 hf1 = __bfloat1622float2(h1);
            __nv_bfloat162 l0 = __floats2bfloat162_rn(vx - hf0.x, vy - hf0.y);
            __nv_bfloat162 l1 = __floats2bfloat162_rn(vz - hf1.x, vw - hf1.y);
            int w = r * GROW + c4 * 2;
            sAh[w]     = *reinterpret_cast<uint32_t*>(&h0);
            sAh[w + 1] = *reinterpret_cast<uint32_t*>(&h1);
            sAl[w]     = *reinterpret_cast<uint32_t*>(&l0);
            sAl[w + 1] = *reinterpret_cast<uint32_t*>(&l1);
        }
        #pragma unroll
        for (int i = 0; i < 2; i++) {
            int id = tid + i * 256;
            int r = id >> 2, gg = id & 3;
            *reinterpret_cast<uint4*>(&sBh[r * GROW + gg * 4]) = pbh[i];
            *reinterpret_cast<uint4*>(&sBl[r * GROW + gg * 4]) = pbl[i];
        }
        __syncthreads();

        // ---- prefetch next chunk (overlaps with mma below)
        if (c + 1 < nch) {
            const int k0 = (c + 1) << 5;
            #pragma unroll
            for (int i = 0; i < 4; i++) {
                int id = tid + i * 256;
                int r = id >> 3, c4 = id & 7;
                pa[i] = *reinterpret_cast<const float4*>(A + (size_t)(m0 + r) * K + k0 + c4 * 4);
            }
            #pragma unroll
            for (int i = 0; i < 2; i++) {
                int id = tid + i * 256;
                int r = id >> 2, gg = id & 3;
                pbh[i] = *reinterpret_cast<const uint4*>(Bh + (size_t)(n0 + r) * K + k0 + gg * 8);
                pbl[i] = *reinterpret_cast<const uint4*>(Bl + (size_t)(n0 + r) * K + k0 + gg * 8);
            }
        }

        // ---- mma over this chunk: 2 k16 steps
        #pragma unroll
        for (int ks = 0; ks < 2; ks++) {
            uint32_t ah[4][4], al[4][4];
            #pragma unroll
            for (int mt = 0; mt < 4; mt++) {
                int w0 = (wm + mt * 16 + g) * GROW + ks * 8 + tg;
                ah[mt][0] = sAh[w0];
                ah[mt][1] = sAh[w0 + 8 * GROW];
                ah[mt][2] = sAh[w0 + 4];
                ah[mt][3] = sAh[w0 + 8 * GROW + 4];
                al[mt][0] = sAl[w0];
                al[mt][1] = sAl[w0 + 8 * GROW];
                al[mt][2] = sAl[w0 + 4];
                al[mt][3] = sAl[w0 + 8 * GROW + 4];
            }
            #pragma unroll
            for (int nt = 0; nt < 4; nt++) {
                int w0 = (wn + nt * 8 + g) * GROW + ks * 8 + tg;
                uint32_t bh0 = sBh[w0], bh1 = sBh[w0 + 4];
                uint32_t bl0 = sBl[w0], bl1 = sBl[w0 + 4];
                #pragma unroll
                for (int mt = 0; mt < 4; mt++) {
                    MMA_BF16(acc[mt][nt], ah[mt], bh0, bh1);
                    MMA_BF16(acc[mt][nt], ah[mt], bl0, bl1);
                    MMA_BF16(acc[mt][nt], al[mt], bh0, bh1);
                }
            }
        }
        __syncthreads();
    }

    // ---- epilogue
    #pragma unroll
    for (int mt = 0; mt < 4; mt++) {
        const int r = m0 + wm + mt * 16 + g;
        #pragma unroll
        for (int nt = 0; nt < 4; nt++) {
            const int cc = n0 + wn + nt * 8 + tg * 2;
            if (MODE == 0) {
                float2 v0 = make_float2(acc[mt][nt][0], acc[mt][nt][1]);
                float2 v1 = make_float2(acc[mt][nt][2], acc[mt][nt][3]);
                if (bias) {
                    float b0 = bias[cc], b1 = bias[cc + 1];
                    v0.x += b0; v0.y += b1;
                    v1.x += b0; v1.y += b1;
                }
                *reinterpret_cast<float2*>(C + (size_t)r * N + cc)       = v0;
                *reinterpret_cast<float2*>(C + (size_t)(r + 8) * N + cc) = v1;
            } else if (MODE == 1) {        // Q: single fp16
                #pragma unroll
                for (int rr = 0; rr < 2; rr++) {
                    __half2 h = __floats2half2_rn(acc[mt][nt][rr * 2], acc[mt][nt][rr * 2 + 1]);
                    size_t idx = (size_t)(r + rr * 8) * N + cc;
                    *reinterpret_cast<uint32_t*>(Ch + idx) = *reinterpret_cast<uint32_t*>(&h);
                }
            } else if (MODE == 2) {        // K: fp16 hi/lo
                #pragma unroll
                for (int rr = 0; rr < 2; rr++) {
                    float v0 = acc[mt][nt][rr * 2], v1 = acc[mt][nt][rr * 2 + 1];
                    __half2 h = __floats2half2_rn(v0, v1);
                    float2 hf = __half22float2(h);
                    __half2 l = __floats2half2_rn(v0 - hf.x, v1 - hf.y);
                    size_t idx = (size_t)(r + rr * 8) * N + cc;
                    *reinterpret_cast<uint32_t*>(Ch + idx) = *reinterpret_cast<uint32_t*>(&h);
                    *reinterpret_cast<uint32_t*>(Cl + idx) = *reinterpret_cast<uint32_t*>(&l);
                }
            } else {   // MODE 3: V transposed fp16 hi/lo  Vt[b][col][key]
                #pragma unroll
                for (int rr = 0; rr < 2; rr++) {
                    int rg = r + rr * 8;
                    int bb = rg >> 10, key = rg & (NKK - 1);
                    #pragma unroll
                    for (int jc = 0; jc < 2; jc++) {
                        float v = acc[mt][nt][rr * 2 + jc];
                        __half h = __float2half_rn(v);
                        size_t idx = ((size_t)bb * INNER + cc + jc) * NKK + key;
                        Ch[idx] = h;
                        Cl[idx] = __float2half_rn(v - __half2float(h));
                    }
                }
            }
        }
    }
}

// ---------------------------------------------------------------------------
// HMMA flash attention (fp16, 2-product split). CTA = 128 q x one (b,h).
// 8 warps, warp = 16 q rows; kv tiles of 128. Softmax in exp2 domain
// (log2e folded into Wq). Q single fp16; K,V fp16 hi/lo; P single fp16.
// ---------------------------------------------------------------------------
__device__ __forceinline__ float fast_exp2(float y) {
    y = fmaxf(y, -120.0f);
    float n = rintf(y);
    float f = y - n;
    float p = 1.3333558146e-3f;
    p = fmaf(p, f, 9.6181291076e-3f);
    p = fmaf(p, f, 5.5504108665e-2f);
    p = fmaf(p, f, 2.4022650696e-1f);
    p = fmaf(p, f, 6.9314718056e-1f);
    p = fmaf(p, f, 1.0f);
    return p * __int_as_float(((int)n + 127) << 23);
}

// smem word offsets (uint32 words)
#define AQ_H 0           // Q:  128 rows x 36 words (64 halfs + pad)
#define AK_H 4608
#define AK_L 9216
#define AV_H 13824       // Vt: 64 rows x 68 words (128 halfs + pad)
#define AV_L 18176
#define ATT_WORDS 22528
#define ATT_BYTES (ATT_WORDS * 4)   // 90112 B

__global__ __launch_bounds__(256, 2) void attn_mma_kernel(
    const __half* __restrict__ Qh_,
    const __half* __restrict__ Kh_, const __half* __restrict__ Kl_,
    const __half* __restrict__ Vh_, const __half* __restrict__ Vl_,
    float* __restrict__ AO)
{
    extern __shared__ uint32_t sw[];
    const int tid = threadIdx.x, lane = tid & 31, w = tid >> 5;
    const int g = lane >> 2, tg = lane & 3;
    const int q0 = blockIdx.x * 128;
    const int bh = blockIdx.y, b = bh >> 3, h = bh & 7;

    // ---- load Q tile [128 q][64 d] (single fp16)
    {
        const __half* sq = Qh_ + ((size_t)(b * NQ + q0)) * INNER + h * 64;
        #pragma unroll
        for (int i = 0; i < 4; i++) {
            int id = tid + i * 256;
            int r = id >> 3, u = id & 7;
            uint4 v = *reinterpret_cast<const uint4*>(sq + (size_t)r * INNER + u * 8);
            *reinterpret_cast<uint4*>(&sw[AQ_H + r * 36 + u * 4]) = v;
        }
    }

    float o[8][4] = {};
    float m0 = -1e30f, m1 = -1e30f, l0 = 0.0f, l1 = 0.0f;

    for (int kt = 0; kt < NKK / 128; kt++) {
        if (kt) __syncthreads();         // prior tile's smem reads done

        // ---- load K tile [128 key][64 d] hi/lo
        {
            const __half* sh = Kh_ + ((size_t)(b * NKK + kt * 128)) * INNER + h * 64;
            const __half* sl = Kl_ + ((size_t)(b * NKK + kt * 128)) * INNER + h * 64;
            #pragma unroll
            for (int i = 0; i < 4; i++) {
                int id = tid + i * 256;
                int r = id >> 3, u = id & 7;
                uint4 vh = *reinterpret_cast<const uint4*>(sh + (size_t)r * INNER + u * 8);
                uint4 vl = *reinterpret_cast<const uint4*>(sl + (size_t)r * INNER + u * 8);
                *reinterpret_cast<uint4*>(&sw[AK_H + r * 36 + u * 4]) = vh;
                *reinterpret_cast<uint4*>(&sw[AK_L + r * 36 + u * 4]) = vl;
            }
        }
        // ---- load Vt tile [64 d][128 key] hi/lo
        {
            const __half* sh = Vh_ + ((size_t)(b * INNER + h * 64)) * NKK + kt * 128;
            const __half* sl = Vl_ + ((size_t)(b * INNER + h * 64)) * NKK + kt * 128;
            #pragma unroll
            for (int i = 0; i < 4; i++) {
                int id = tid + i * 256;
                int r = id >> 4, u = id & 15;
                uint4 vh = *reinterpret_cast<const uint4*>(sh + (size_t)r * NKK + u * 8);
                uint4 vl = *reinterpret_cast<const uint4*>(sl + (size_t)r * NKK + u * 8);
                *reinterpret_cast<uint4*>(&sw[AV_H + r * 68 + u * 4]) = vh;
                *reinterpret_cast<uint4*>(&sw[AV_L + r * 68 + u * 4]) = vl;
            }
        }
        __syncthreads();

        // ---- S = Q K^T (2 products: Qh*Kh + Qh*Kl), warp: 16 q x 128 keys
        float acc[16][4] = {};
        #pragma unroll
        for (int ks = 0; ks < 4; ks++) {
            int wq = (w * 16 + g) * 36 + ks * 8 + tg;
            uint32_t qh[4] = { sw[AQ_H + wq], sw[AQ_H + wq + 8 * 36],
                               sw[AQ_H + wq + 4], sw[AQ_H + wq + 8 * 36 + 4] };
            #pragma unroll
            for (int nt = 0; nt < 16; nt++) {
                int wk = (nt * 8 + g) * 36 + ks * 8 + tg;
                uint32_t bh0 = sw[AK_H + wk], bh1 = sw[AK_H + wk + 4];
                uint32_t bl0 = sw[AK_L + wk], bl1 = sw[AK_L + wk + 4];
                MMA_F16(acc[nt], qh, bh0, bh1);
                MMA_F16(acc[nt], qh, bl0, bl1);
            }
        }

        // ---- register online softmax in exp2 domain (rows g and g+8)
        float tm0 = -1e30f, tm1 = -1e30f;
        #pragma unroll
        for (int nt = 0; nt < 16; nt++) {
            tm0 = fmaxf(tm0, fmaxf(acc[nt][0], acc[nt][1]));
            tm1 = fmaxf(tm1, fmaxf(acc[nt][2], acc[nt][3]));
        }
        tm0 = fmaxf(tm0, __shfl_xor_sync(0xffffffffu, tm0, 1));
        tm0 = fmaxf(tm0, __shfl_xor_sync(0xffffffffu, tm0, 2));
        tm1 = fmaxf(tm1, __shfl_xor_sync(0xffffffffu, tm1, 1));
        tm1 = fmaxf(tm1, __shfl_xor_sync(0xffffffffu, tm1, 2));
        float mn0 = fmaxf(m0, tm0), mn1 = fmaxf(m1, tm1);
        float r0 = fast_exp2(m0 - mn0), r1 = fast_exp2(m1 - mn1);
        m0 = mn0; m1 = mn1;
        float s0 = 0.0f, s1 = 0.0f;
        #pragma unroll
        for (int nt = 0; nt < 16; nt++) {
            acc[nt][0] = fast_exp2(acc[nt][0] - mn0); s0 += acc[nt][0];
            acc[nt][1] = fast_exp2(acc[nt][1] - mn0); s0 += acc[nt][1];
            acc[nt][2] = fast_exp2(acc[nt][2] - mn1); s1 += acc[nt][2];
            acc[nt][3] = fast_exp2(acc[nt][3] - mn1); s1 += acc[nt][3];
        }
        s0 += __shfl_xor_sync(0xffffffffu, s0, 1);
        s0 += __shfl_xor_sync(0xffffffffu, s0, 2);
        s1 += __shfl_xor_sync(0xffffffffu, s1, 1);
        s1 += __shfl_xor_sync(0xffffffffu, s1, 2);
        l0 = l0 * r0 + s0;
        l1 = l1 * r1 + s1;
        #pragma unroll
        for (int nt = 0; nt < 8; nt++) {
            o[nt][0] *= r0; o[nt][1] *= r0;
            o[nt][2] *= r1; o[nt][3] *= r1;
        }

        // ---- O += P V (P single fp16; 2 products: P*Vh + P*Vl)
        #pragma unroll
        for (int ks = 0; ks < 8; ks++) {
            uint32_t ah[4];
            {
                __half2 t;
                t = __floats2half2_rn(acc[2 * ks][0],     acc[2 * ks][1]);
                ah[0] = *reinterpret_cast<uint32_t*>(&t);
                t = __floats2half2_rn(acc[2 * ks][2],     acc[2 * ks][3]);
                ah[1] = *reinterpret_cast<uint32_t*>(&t);
                t = __floats2half2_rn(acc[2 * ks + 1][0], acc[2 * ks + 1][1]);
                ah[2] = *reinterpret_cast<uint32_t*>(&t);
                t = __floats2half2_rn(acc[2 * ks + 1][2], acc[2 * ks + 1][3]);
                ah[3] = *reinterpret_cast<uint32_t*>(&t);
            }
            #pragma unroll
            for (int nt = 0; nt < 8; nt++) {
                int wv = (nt * 8 + g) * 68 + ks * 8 + tg;
                uint32_t bh0 = sw[AV_H + wv], bh1 = sw[AV_H + wv + 4];
                uint32_t bl0 = sw[AV_L + wv], bl1 = sw[AV_L + wv + 4];
                MMA_F16(o[nt], ah, bh0, bh1);
                MMA_F16(o[nt], ah, bl0, bl1);
            }
        }
    }

    // ---- epilogue: normalize, store fp32 AO
    float i0 = 1.0f / l0, i1 = 1.0f / l1;
    const int rg = q0 + w * 16 + g;
    #pragma unroll
    for (int nt = 0; nt < 8; nt++) {
        const int col = h * 64 + nt * 8 + tg * 2;
        float2 v0 = make_float2(o[nt][0] * i0, o[nt][1] * i0);
        float2 v1 = make_float2(o[nt][2] * i1, o[nt][3] * i1);
        *reinterpret_cast<float2*>(AO + (size_t)(b * NQ + rg) * INNER + col)     = v0;
        *reinterpret_cast<float2*>(AO + (size_t)(b * NQ + rg + 8) * INNER + col) = v1;
    }
}

// ---------------------------------------------------------------------------
// Launcher
// ---------------------------------------------------------------------------
extern "C" void kernel_launch(void* const* d_in, const int* in_sizes, int n_in,
                              void* d_out, int out_size)
{
    const float* x   = (const float*)d_in[0];  // [4,2048,512]
    const float* ctx = (const float*)d_in[1];  // [4,1024,768]
    const float* Wq  = (const float*)d_in[2];  // [512,512]
    const float* Wk  = (const float*)d_in[3];  // [768,512]
    const float* Wv  = (const float*)d_in[4];  // [768,512]
    const float* Wo  = (const float*)d_in[5];  // [512,512]
    const float* bo  = (const float*)d_in[6];  // [512]
    float* out = (float*)d_out;

    float* AOb;
    cudaGetSymbolAddress((void**)&AOb, g_AO);

    __half *Qh, *Kh, *Kl, *Vth, *Vtl;
    cudaGetSymbolAddress((void**)&Qh,  g_Qh);
    cudaGetSymbolAddress((void**)&Kh,  g_Kh);   cudaGetSymbolAddress((void**)&Kl,  g_Kl);
    cudaGetSymbolAddress((void**)&Vth, g_Vth);  cudaGetSymbolAddress((void**)&Vtl, g_Vtl);

    __nv_bfloat16 *WqTh, *WqTl, *WkTh, *WkTl, *WvTh, *WvTl, *WoTh, *WoTl;
    cudaGetSymbolAddress((void**)&WqTh, g_WqTh); cudaGetSymbolAddress((void**)&WqTl, g_WqTl);
    cudaGetSymbolAddress((void**)&WkTh, g_WkTh); cudaGetSymbolAddress((void**)&WkTl, g_WkTl);
    cudaGetSymbolAddress((void**)&WvTh, g_WvTh); cudaGetSymbolAddress((void**)&WvTl, g_WvTl);
    cudaGetSymbolAddress((void**)&WoTh, g_WoTh); cudaGetSymbolAddress((void**)&WoTl, g_WoTl);

    cudaFuncSetAttribute(attn_mma_kernel,
                         cudaFuncAttributeMaxDynamicSharedMemorySize, ATT_BYTES);

    // --- all weight transposes + hi/lo splits in one launch ---
    splitT_all_kernel<<<1280, dim3(32, 8)>>>(
        Wq, Wk, Wv, Wo, WqTh, WqTl, WkTh, WkTl, WvTh, WvTl, WoTh, WoTl);

    // --- projections (epilogues emit fp16 operands for attention) ---
    hgemm_kernel<1><<<dim3(INNER / 128, (NB * NQ) / 128), 256>>>(
        x, WqTh, WqTl, nullptr, nullptr, Qh, nullptr, NB * NQ, DQ, INNER);
    hgemm_kernel<2><<<dim3(INNER / 128, (NB * NKK) / 128), 256>>>(
        ctx, WkTh, WkTl, nullptr, nullptr, Kh, Kl, NB * NKK, DC, INNER);
    hgemm_kernel<3><<<dim3(INNER / 128, (NB * NKK) / 128), 256>>>(
        ctx, WvTh, WvTl, nullptr, nullptr, Vth, Vtl, NB * NKK, DC, INNER);

    // --- fused attention on tensor cores (fp16, 2-product) ---
    attn_mma_kernel<<<dim3(NQ / 128, NB * NHEAD), 256, ATT_BYTES>>>(
        Qh, Kh, Kl, Vth, Vtl, AOb);

    // --- output projection (+bias) ---
    hgemm_kernel<0><<<dim3(DQ / 128, (NB * NQ) / 128), 256>>>(
        AOb, WoTh, WoTl, bo, out, nullptr, nullptr, NB * NQ, INNER, DQ);
}

// round 13
// speedup vs baseline: 4.0313x; 1.1084x over previous
#include <cuda_runtime.h>
#include <cuda_fp16.h>
#include <cstdint>
#include <cstddef>

// Problem constants
#define NB    4
#define NQ    2048
#define DQ    512
#define NKK   1024
#define DC    768
#define NHEAD 8
#define DHEAD 64
#define INNER 512   // NHEAD*DHEAD

// log2(e) * DIM_HEAD^-0.5  (folded into Wq so softmax runs in exp2 domain)
#define QSCALE 0.1803368801111204f

// ---------------------------------------------------------------------------
// Scratch (device globals — no allocation allowed)
// ---------------------------------------------------------------------------
__device__ float g_AO[NB * NQ  * INNER];

// attention operands produced by projection GEMM epilogues (fp16)
__device__ __half g_Qh [NB * NQ  * INNER];                          // single
__device__ __half g_Kh [NB * NKK * INNER], g_Kl [NB * NKK * INNER]; // hi/lo
__device__ __half g_Vth[NB * INNER * NKK], g_Vtl[NB * INNER * NKK]; // hi/lo, [b][hd][key]

// transposed + split weights (fp16 hi/lo): WT[n][k] = W[k][n]
__device__ __half g_WqTh[INNER * DQ],  g_WqTl[INNER * DQ];
__device__ __half g_WkTh[INNER * DC],  g_WkTl[INNER * DC];
__device__ __half g_WvTh[INNER * DC],  g_WvTl[INNER * DC];
__device__ __half g_WoTh[DQ * INNER],  g_WoTl[DQ * INNER];

// ---------------------------------------------------------------------------
// Batched transpose + split for all 4 weights in one launch.
// Per weight: W[K][N] -> WT hi/lo [N][K] (fp16), with scale.
// ---------------------------------------------------------------------------
__device__ __forceinline__ void splitT_tile(
    const float* __restrict__ W, __half* __restrict__ hT,
    __half* __restrict__ lT, int K, int N, float scale,
    int n0, int k0, int tx, int ty, float (*t)[33])
{
    #pragma unroll
    for (int r = ty; r < 32; r += 8)
        t[r][tx] = W[(size_t)(k0 + r) * N + n0 + tx];
    __syncthreads();
    #pragma unroll
    for (int r = ty; r < 32; r += 8) {
        float v = t[tx][r] * scale;       // element (n = n0+r, k = k0+tx)
        __half h = __float2half_rn(v);
        size_t idx = (size_t)(n0 + r) * K + k0 + tx;
        hT[idx] = h;
        lT[idx] = __float2half_rn(v - __half2float(h));
    }
}

__global__ void splitT_all_kernel(
    const float* __restrict__ Wq, const float* __restrict__ Wk,
    const float* __restrict__ Wv, const float* __restrict__ Wo,
    __half* __restrict__ WqTh, __half* __restrict__ WqTl,
    __half* __restrict__ WkTh, __half* __restrict__ WkTl,
    __half* __restrict__ WvTh, __half* __restrict__ WvTl,
    __half* __restrict__ WoTh, __half* __restrict__ WoTl)
{
    __shared__ float t[32][33];
    const int tx = threadIdx.x, ty = threadIdx.y;
    int id = blockIdx.x;
    if (id < 256) {
        int n0 = (id & 15) * 32, k0 = (id >> 4) * 32;
        splitT_tile(Wq, WqTh, WqTl, DQ, INNER, QSCALE, n0, k0, tx, ty, t);
    } else if (id < 640) {
        id -= 256;
        int n0 = (id & 15) * 32, k0 = (id >> 4) * 32;
        splitT_tile(Wk, WkTh, WkTl, DC, INNER, 1.0f, n0, k0, tx, ty, t);
    } else if (id < 1024) {
        id -= 640;
        int n0 = (id & 15) * 32, k0 = (id >> 4) * 32;
        splitT_tile(Wv, WvTh, WvTl, DC, INNER, 1.0f, n0, k0, tx, ty, t);
    } else {
        id -= 1024;
        int n0 = (id & 15) * 32, k0 = (id >> 4) * 32;
        splitT_tile(Wo, WoTh, WoTl, INNER, DQ, 1.0f, n0, k0, tx, ty, t);
    }
}

// ---------------------------------------------------------------------------
// HMMA fp16 2-product GEMM: C = A[M,K](fp32 -> single fp16 in-kernel) @ B^T,
// B stored [N,K] pre-split fp16 hi/lo. 128x64 CTA tile, BK=32, 8 warps
// (4m x 2n), warp tile 32x32, m16n8k16, fp32 accum. 2 CTAs/SM.
// Epilogue MODE: 0 = fp32 C (+bias); 1 = fp16 single (Q);
//                2 = fp16 hi/lo natural (K); 3 = fp16 hi/lo transposed-V.
// ---------------------------------------------------------------------------
#define GROW 20   // words per smem row (32 fp16 = 16 words + 4 pad)

#define MMA_F16(d, a, b0, b1) \
    asm volatile("mma.sync.aligned.m16n8k16.row.col.f32.f16.f16.f32 " \
        "{%0,%1,%2,%3}, {%4,%5,%6,%7}, {%8,%9}, {%0,%1,%2,%3};" \
        : "+f"((d)[0]), "+f"((d)[1]), "+f"((d)[2]), "+f"((d)[3]) \
        : "r"((a)[0]), "r"((a)[1]), "r"((a)[2]), "r"((a)[3]), \
          "r"(b0), "r"(b1))

template <int MODE>
__global__ __launch_bounds__(256, 2) void hgemm_kernel(
    const float* __restrict__ A,
    const __half* __restrict__ Bh, const __half* __restrict__ Bl,
    const float* __restrict__ bias, float* __restrict__ C,
    __half* __restrict__ Ch, __half* __restrict__ Cl,
    int M, int K, int N)
{
    __shared__ __align__(16) uint32_t sA [128 * GROW];
    __shared__ __align__(16) uint32_t sBh[64 * GROW];
    __shared__ __align__(16) uint32_t sBl[64 * GROW];

    const int tid  = threadIdx.x;
    const int lane = tid & 31, wid = tid >> 5;
    const int wm = (wid >> 1) * 32;     // warp m base: 0,32,64,96
    const int wn = (wid & 1) * 32;      // warp n base: 0 or 32
    const int g  = lane >> 2, tg = lane & 3;
    const int m0 = blockIdx.y * 128, n0 = blockIdx.x * 64;

    const int nch = K >> 5;

    float4 pa[4];
    uint4  pbh, pbl;

    // prefetch chunk 0
    {
        #pragma unroll
        for (int i = 0; i < 4; i++) {
            int id = tid + i * 256;
            int r = id >> 3, c4 = id & 7;
            pa[i] = *reinterpret_cast<const float4*>(A + (size_t)(m0 + r) * K + c4 * 4);
        }
        int r = tid >> 2, gg = tid & 3;
        pbh = *reinterpret_cast<const uint4*>(Bh + (size_t)(n0 + r) * K + gg * 8);
        pbl = *reinterpret_cast<const uint4*>(Bl + (size_t)(n0 + r) * K + gg * 8);
    }

    float acc[2][4][4] = {};   // [mt][nt][reg]

    for (int c = 0; c < nch; c++) {
        // ---- store prefetched chunk to smem (fp32 -> single fp16 for A)
        #pragma unroll
        for (int i = 0; i < 4; i++) {
            int id = tid + i * 256;
            int r = id >> 3, c4 = id & 7;
            __half2 h0 = __floats2half2_rn(pa[i].x, pa[i].y);
            __half2 h1 = __floats2half2_rn(pa[i].z, pa[i].w);
            int w = r * GROW + c4 * 2;
            sA[w]     = *reinterpret_cast<uint32_t*>(&h0);
            sA[w + 1] = *reinterpret_cast<uint32_t*>(&h1);
        }
        {
            int r = tid >> 2, gg = tid & 3;
            *reinterpret_cast<uint4*>(&sBh[r * GROW + gg * 4]) = pbh;
            *reinterpret_cast<uint4*>(&sBl[r * GROW + gg * 4]) = pbl;
        }
        __syncthreads();

        // ---- prefetch next chunk (overlaps with mma below)
        if (c + 1 < nch) {
            const int k0 = (c + 1) << 5;
            #pragma unroll
            for (int i = 0; i < 4; i++) {
                int id = tid + i * 256;
                int r = id >> 3, c4 = id & 7;
                pa[i] = *reinterpret_cast<const float4*>(A + (size_t)(m0 + r) * K + k0 + c4 * 4);
            }
            int r = tid >> 2, gg = tid & 3;
            pbh = *reinterpret_cast<const uint4*>(Bh + (size_t)(n0 + r) * K + k0 + gg * 8);
            pbl = *reinterpret_cast<const uint4*>(Bl + (size_t)(n0 + r) * K + k0 + gg * 8);
        }

        // ---- mma over this chunk: 2 k16 steps, 2 products (Bh, Bl)
        #pragma unroll
        for (int ks = 0; ks < 2; ks++) {
            uint32_t ah[2][4];
            #pragma unroll
            for (int mt = 0; mt < 2; mt++) {
                int w0 = (wm + mt * 16 + g) * GROW + ks * 8 + tg;
                ah[mt][0] = sA[w0];
                ah[mt][1] = sA[w0 + 8 * GROW];
                ah[mt][2] = sA[w0 + 4];
                ah[mt][3] = sA[w0 + 8 * GROW + 4];
            }
            #pragma unroll
            for (int nt = 0; nt < 4; nt++) {
                int w0 = (wn + nt * 8 + g) * GROW + ks * 8 + tg;
                uint32_t bh0 = sBh[w0], bh1 = sBh[w0 + 4];
                uint32_t bl0 = sBl[w0], bl1 = sBl[w0 + 4];
                #pragma unroll
                for (int mt = 0; mt < 2; mt++) {
                    MMA_F16(acc[mt][nt], ah[mt], bh0, bh1);
                    MMA_F16(acc[mt][nt], ah[mt], bl0, bl1);
                }
            }
        }
        __syncthreads();
    }

    // ---- epilogue
    #pragma unroll
    for (int mt = 0; mt < 2; mt++) {
        const int r = m0 + wm + mt * 16 + g;
        #pragma unroll
        for (int nt = 0; nt < 4; nt++) {
            const int cc = n0 + wn + nt * 8 + tg * 2;
            if (MODE == 0) {
                float2 v0 = make_float2(acc[mt][nt][0], acc[mt][nt][1]);
                float2 v1 = make_float2(acc[mt][nt][2], acc[mt][nt][3]);
                if (bias) {
                    float b0 = bias[cc], b1 = bias[cc + 1];
                    v0.x += b0; v0.y += b1;
                    v1.x += b0; v1.y += b1;
                }
                *reinterpret_cast<float2*>(C + (size_t)r * N + cc)       = v0;
                *reinterpret_cast<float2*>(C + (size_t)(r + 8) * N + cc) = v1;
            } else if (MODE == 1) {        // Q: single fp16
                #pragma unroll
                for (int rr = 0; rr < 2; rr++) {
                    __half2 h = __floats2half2_rn(acc[mt][nt][rr * 2], acc[mt][nt][rr * 2 + 1]);
                    size_t idx = (size_t)(r + rr * 8) * N + cc;
                    *reinterpret_cast<uint32_t*>(Ch + idx) = *reinterpret_cast<uint32_t*>(&h);
                }
            } else if (MODE == 2) {        // K: fp16 hi/lo
                #pragma unroll
                for (int rr = 0; rr < 2; rr++) {
                    float v0 = acc[mt][nt][rr * 2], v1 = acc[mt][nt][rr * 2 + 1];
                    __half2 h = __floats2half2_rn(v0, v1);
                    float2 hf = __half22float2(h);
                    __half2 l = __floats2half2_rn(v0 - hf.x, v1 - hf.y);
                    size_t idx = (size_t)(r + rr * 8) * N + cc;
                    *reinterpret_cast<uint32_t*>(Ch + idx) = *reinterpret_cast<uint32_t*>(&h);
                    *reinterpret_cast<uint32_t*>(Cl + idx) = *reinterpret_cast<uint32_t*>(&l);
                }
            } else {   // MODE 3: V transposed fp16 hi/lo  Vt[b][col][key]
                #pragma unroll
                for (int rr = 0; rr < 2; rr++) {
                    int rg = r + rr * 8;
                    int bb = rg >> 10, key = rg & (NKK - 1);
                    #pragma unroll
                    for (int jc = 0; jc < 2; jc++) {
                        float v = acc[mt][nt][rr * 2 + jc];
                        __half h = __float2half_rn(v);
                        size_t idx = ((size_t)bb * INNER + cc + jc) * NKK + key;
                        Ch[idx] = h;
                        Cl[idx] = __float2half_rn(v - __half2float(h));
                    }
                }
            }
        }
    }
}

// ---------------------------------------------------------------------------
// HMMA flash attention (fp16, 2-product split). CTA = 128 q x one (b,h).
// 8 warps, warp = 16 q rows; kv tiles of 128. Softmax in exp2 domain
// (log2e folded into Wq). Q single fp16; K,V fp16 hi/lo; P single fp16.
// ---------------------------------------------------------------------------
__device__ __forceinline__ float fast_exp2(float y) {
    y = fmaxf(y, -120.0f);
    float n = rintf(y);
    float f = y - n;
    float p = 1.3333558146e-3f;
    p = fmaf(p, f, 9.6181291076e-3f);
    p = fmaf(p, f, 5.5504108665e-2f);
    p = fmaf(p, f, 2.4022650696e-1f);
    p = fmaf(p, f, 6.9314718056e-1f);
    p = fmaf(p, f, 1.0f);
    return p * __int_as_float(((int)n + 127) << 23);
}

// smem word offsets (uint32 words)
#define AQ_H 0           // Q:  128 rows x 36 words (64 halfs + pad)
#define AK_H 4608
#define AK_L 9216
#define AV_H 13824       // Vt: 64 rows x 68 words (128 halfs + pad)
#define AV_L 18176
#define ATT_WORDS 22528
#define ATT_BYTES (ATT_WORDS * 4)   // 90112 B

__global__ __launch_bounds__(256, 2) void attn_mma_kernel(
    const __half* __restrict__ Qh_,
    const __half* __restrict__ Kh_, const __half* __restrict__ Kl_,
    const __half* __restrict__ Vh_, const __half* __restrict__ Vl_,
    float* __restrict__ AO)
{
    extern __shared__ uint32_t sw[];
    const int tid = threadIdx.x, lane = tid & 31, w = tid >> 5;
    const int g = lane >> 2, tg = lane & 3;
    const int q0 = blockIdx.x * 128;
    const int bh = blockIdx.y, b = bh >> 3, h = bh & 7;

    // ---- load Q tile [128 q][64 d] (single fp16)
    {
        const __half* sq = Qh_ + ((size_t)(b * NQ + q0)) * INNER + h * 64;
        #pragma unroll
        for (int i = 0; i < 4; i++) {
            int id = tid + i * 256;
            int r = id >> 3, u = id & 7;
            uint4 v = *reinterpret_cast<const uint4*>(sq + (size_t)r * INNER + u * 8);
            *reinterpret_cast<uint4*>(&sw[AQ_H + r * 36 + u * 4]) = v;
        }
    }

    float o[8][4] = {};
    float m0 = -1e30f, m1 = -1e30f, l0 = 0.0f, l1 = 0.0f;

    for (int kt = 0; kt < NKK / 128; kt++) {
        if (kt) __syncthreads();         // prior tile's smem reads done

        // ---- load K tile [128 key][64 d] hi/lo
        {
            const __half* sh = Kh_ + ((size_t)(b * NKK + kt * 128)) * INNER + h * 64;
            const __half* sl = Kl_ + ((size_t)(b * NKK + kt * 128)) * INNER + h * 64;
            #pragma unroll
            for (int i = 0; i < 4; i++) {
                int id = tid + i * 256;
                int r = id >> 3, u = id & 7;
                uint4 vh = *reinterpret_cast<const uint4*>(sh + (size_t)r * INNER + u * 8);
                uint4 vl = *reinterpret_cast<const uint4*>(sl + (size_t)r * INNER + u * 8);
                *reinterpret_cast<uint4*>(&sw[AK_H + r * 36 + u * 4]) = vh;
                *reinterpret_cast<uint4*>(&sw[AK_L + r * 36 + u * 4]) = vl;
            }
        }
        // ---- load Vt tile [64 d][128 key] hi/lo
        {
            const __half* sh = Vh_ + ((size_t)(b * INNER + h * 64)) * NKK + kt * 128;
            const __half* sl = Vl_ + ((size_t)(b * INNER + h * 64)) * NKK + kt * 128;
            #pragma unroll
            for (int i = 0; i < 4; i++) {
                int id = tid + i * 256;
                int r = id >> 4, u = id & 15;
                uint4 vh = *reinterpret_cast<const uint4*>(sh + (size_t)r * NKK + u * 8);
                uint4 vl = *reinterpret_cast<const uint4*>(sl + (size_t)r * NKK + u * 8);
                *reinterpret_cast<uint4*>(&sw[AV_H + r * 68 + u * 4]) = vh;
                *reinterpret_cast<uint4*>(&sw[AV_L + r * 68 + u * 4]) = vl;
            }
        }
        __syncthreads();

        // ---- S = Q K^T (2 products: Qh*Kh + Qh*Kl), warp: 16 q x 128 keys
        float acc[16][4] = {};
        #pragma unroll
        for (int ks = 0; ks < 4; ks++) {
            int wq = (w * 16 + g) * 36 + ks * 8 + tg;
            uint32_t qh[4] = { sw[AQ_H + wq], sw[AQ_H + wq + 8 * 36],
                               sw[AQ_H + wq + 4], sw[AQ_H + wq + 8 * 36 + 4] };
            #pragma unroll
            for (int nt = 0; nt < 16; nt++) {
                int wk = (nt * 8 + g) * 36 + ks * 8 + tg;
                uint32_t bh0 = sw[AK_H + wk], bh1 = sw[AK_H + wk + 4];
                uint32_t bl0 = sw[AK_L + wk], bl1 = sw[AK_L + wk + 4];
                MMA_F16(acc[nt], qh, bh0, bh1);
                MMA_F16(acc[nt], qh, bl0, bl1);
            }
        }

        // ---- register online softmax in exp2 domain (rows g and g+8)
        float tm0 = -1e30f, tm1 = -1e30f;
        #pragma unroll
        for (int nt = 0; nt < 16; nt++) {
            tm0 = fmaxf(tm0, fmaxf(acc[nt][0], acc[nt][1]));
            tm1 = fmaxf(tm1, fmaxf(acc[nt][2], acc[nt][3]));
        }
        tm0 = fmaxf(tm0, __shfl_xor_sync(0xffffffffu, tm0, 1));
        tm0 = fmaxf(tm0, __shfl_xor_sync(0xffffffffu, tm0, 2));
        tm1 = fmaxf(tm1, __shfl_xor_sync(0xffffffffu, tm1, 1));
        tm1 = fmaxf(tm1, __shfl_xor_sync(0xffffffffu, tm1, 2));
        float mn0 = fmaxf(m0, tm0), mn1 = fmaxf(m1, tm1);
        float r0 = fast_exp2(m0 - mn0), r1 = fast_exp2(m1 - mn1);
        m0 = mn0; m1 = mn1;
        float s0 = 0.0f, s1 = 0.0f;
        #pragma unroll
        for (int nt = 0; nt < 16; nt++) {
            acc[nt][0] = fast_exp2(acc[nt][0] - mn0); s0 += acc[nt][0];
            acc[nt][1] = fast_exp2(acc[nt][1] - mn0); s0 += acc[nt][1];
            acc[nt][2] = fast_exp2(acc[nt][2] - mn1); s1 += acc[nt][2];
            acc[nt][3] = fast_exp2(acc[nt][3] - mn1); s1 += acc[nt][3];
        }
        s0 += __shfl_xor_sync(0xffffffffu, s0, 1);
        s0 += __shfl_xor_sync(0xffffffffu, s0, 2);
        s1 += __shfl_xor_sync(0xffffffffu, s1, 1);
        s1 += __shfl_xor_sync(0xffffffffu, s1, 2);
        l0 = l0 * r0 + s0;
        l1 = l1 * r1 + s1;
        #pragma unroll
        for (int nt = 0; nt < 8; nt++) {
            o[nt][0] *= r0; o[nt][1] *= r0;
            o[nt][2] *= r1; o[nt][3] *= r1;
        }

        // ---- O += P V (P single fp16; 2 products: P*Vh + P*Vl)
        #pragma unroll
        for (int ks = 0; ks < 8; ks++) {
            uint32_t ah[4];
            {
                __half2 t;
                t = __floats2half2_rn(acc[2 * ks][0],     acc[2 * ks][1]);
                ah[0] = *reinterpret_cast<uint32_t*>(&t);
                t = __floats2half2_rn(acc[2 * ks][2],     acc[2 * ks][3]);
                ah[1] = *reinterpret_cast<uint32_t*>(&t);
                t = __floats2half2_rn(acc[2 * ks + 1][0], acc[2 * ks + 1][1]);
                ah[2] = *reinterpret_cast<uint32_t*>(&t);
                t = __floats2half2_rn(acc[2 * ks + 1][2], acc[2 * ks + 1][3]);
                ah[3] = *reinterpret_cast<uint32_t*>(&t);
            }
            #pragma unroll
            for (int nt = 0; nt < 8; nt++) {
                int wv = (nt * 8 + g) * 68 + ks * 8 + tg;
                uint32_t bh0 = sw[AV_H + wv], bh1 = sw[AV_H + wv + 4];
                uint32_t bl0 = sw[AV_L + wv], bl1 = sw[AV_L + wv + 4];
                MMA_F16(o[nt], ah, bh0, bh1);
                MMA_F16(o[nt], ah, bl0, bl1);
            }
        }
    }

    // ---- epilogue: normalize, store fp32 AO
    float i0 = 1.0f / l0, i1 = 1.0f / l1;
    const int rg = q0 + w * 16 + g;
    #pragma unroll
    for (int nt = 0; nt < 8; nt++) {
        const int col = h * 64 + nt * 8 + tg * 2;
        float2 v0 = make_float2(o[nt][0] * i0, o[nt][1] * i0);
        float2 v1 = make_float2(o[nt][2] * i1, o[nt][3] * i1);
        *reinterpret_cast<float2*>(AO + (size_t)(b * NQ + rg) * INNER + col)     = v0;
        *reinterpret_cast<float2*>(AO + (size_t)(b * NQ + rg + 8) * INNER + col) = v1;
    }
}

// ---------------------------------------------------------------------------
// Launcher
// ---------------------------------------------------------------------------
extern "C" void kernel_launch(void* const* d_in, const int* in_sizes, int n_in,
                              void* d_out, int out_size)
{
    const float* x   = (const float*)d_in[0];  // [4,2048,512]
    const float* ctx = (const float*)d_in[1];  // [4,1024,768]
    const float* Wq  = (const float*)d_in[2];  // [512,512]
    const float* Wk  = (const float*)d_in[3];  // [768,512]
    const float* Wv  = (const float*)d_in[4];  // [768,512]
    const float* Wo  = (const float*)d_in[5];  // [512,512]
    const float* bo  = (const float*)d_in[6];  // [512]
    float* out = (float*)d_out;

    float* AOb;
    cudaGetSymbolAddress((void**)&AOb, g_AO);

    __half *Qh, *Kh, *Kl, *Vth, *Vtl;
    cudaGetSymbolAddress((void**)&Qh,  g_Qh);
    cudaGetSymbolAddress((void**)&Kh,  g_Kh);   cudaGetSymbolAddress((void**)&Kl,  g_Kl);
    cudaGetSymbolAddress((void**)&Vth, g_Vth);  cudaGetSymbolAddress((void**)&Vtl, g_Vtl);

    __half *WqTh, *WqTl, *WkTh, *WkTl, *WvTh, *WvTl, *WoTh, *WoTl;
    cudaGetSymbolAddress((void**)&WqTh, g_WqTh); cudaGetSymbolAddress((void**)&WqTl, g_WqTl);
    cudaGetSymbolAddress((void**)&WkTh, g_WkTh); cudaGetSymbolAddress((void**)&WkTl, g_WkTl);
    cudaGetSymbolAddress((void**)&WvTh, g_WvTh); cudaGetSymbolAddress((void**)&WvTl, g_WvTl);
    cudaGetSymbolAddress((void**)&WoTh, g_WoTh); cudaGetSymbolAddress((void**)&WoTl, g_WoTl);

    cudaFuncSetAttribute(attn_mma_kernel,
                         cudaFuncAttributeMaxDynamicSharedMemorySize, ATT_BYTES);

    // --- all weight transposes + hi/lo splits in one launch ---
    splitT_all_kernel<<<1280, dim3(32, 8)>>>(
        Wq, Wk, Wv, Wo, WqTh, WqTl, WkTh, WkTl, WvTh, WvTl, WoTh, WoTl);

    // --- projections (epilogues emit fp16 operands for attention) ---
    hgemm_kernel<1><<<dim3(INNER / 64, (NB * NQ) / 128), 256>>>(
        x, WqTh, WqTl, nullptr, nullptr, Qh, nullptr, NB * NQ, DQ, INNER);
    hgemm_kernel<2><<<dim3(INNER / 64, (NB * NKK) / 128), 256>>>(
        ctx, WkTh, WkTl, nullptr, nullptr, Kh, Kl, NB * NKK, DC, INNER);
    hgemm_kernel<3><<<dim3(INNER / 64, (NB * NKK) / 128), 256>>>(
        ctx, WvTh, WvTl, nullptr, nullptr, Vth, Vtl, NB * NKK, DC, INNER);

    // --- fused attention on tensor cores (fp16, 2-product) ---
    attn_mma_kernel<<<dim3(NQ / 128, NB * NHEAD), 256, ATT_BYTES>>>(
        Qh, Kh, Kl, Vth, Vtl, AOb);

    // --- output projection (+bias) ---
    hgemm_kernel<0><<<dim3(DQ / 64, (NB * NQ) / 128), 256>>>(
        AOb, WoTh, WoTl, bo, out, nullptr, nullptr, NB * NQ, INNER, DQ);
}

// round 15
// speedup vs baseline: 4.1229x; 1.0227x over previous
#include <cuda_runtime.h>
#include <cuda_fp16.h>
#include <cstdint>
#include <cstddef>

// Problem constants
#define NB    4
#define NQ    2048
#define DQ    512
#define NKK   1024
#define DC    768
#define NHEAD 8
#define DHEAD 64
#define INNER 512   // NHEAD*DHEAD

// log2(e) * DIM_HEAD^-0.5  (folded into Wq so softmax runs in exp2 domain)
#define QSCALE 0.1803368801111204f

// ---------------------------------------------------------------------------
// Scratch (device globals — no allocation allowed)
// ---------------------------------------------------------------------------
__device__ float g_AO[NB * NQ  * INNER];

// attention operands produced by projection GEMM epilogues (fp16)
__device__ __half g_Qh [NB * NQ  * INNER];                          // single
__device__ __half g_Kh [NB * NKK * INNER], g_Kl [NB * NKK * INNER]; // hi/lo
__device__ __half g_Vth[NB * INNER * NKK], g_Vtl[NB * INNER * NKK]; // hi/lo, [b][hd][key]

// transposed + split weights (fp16 hi/lo): WT[n][k] = W[k][n]
__device__ __half g_WqTh[INNER * DQ],  g_WqTl[INNER * DQ];
__device__ __half g_WkTh[INNER * DC],  g_WkTl[INNER * DC];
__device__ __half g_WvTh[INNER * DC],  g_WvTl[INNER * DC];
__device__ __half g_WoTh[DQ * INNER],  g_WoTl[DQ * INNER];

// ---------------------------------------------------------------------------
// Batched transpose + split for all 4 weights in one launch.
// ---------------------------------------------------------------------------
__device__ __forceinline__ void splitT_tile(
    const float* __restrict__ W, __half* __restrict__ hT,
    __half* __restrict__ lT, int K, int N, float scale,
    int n0, int k0, int tx, int ty, float (*t)[33])
{
    #pragma unroll
    for (int r = ty; r < 32; r += 8)
        t[r][tx] = W[(size_t)(k0 + r) * N + n0 + tx];
    __syncthreads();
    #pragma unroll
    for (int r = ty; r < 32; r += 8) {
        float v = t[tx][r] * scale;       // element (n = n0+r, k = k0+tx)
        __half h = __float2half_rn(v);
        size_t idx = (size_t)(n0 + r) * K + k0 + tx;
        hT[idx] = h;
        lT[idx] = __float2half_rn(v - __half2float(h));
    }
}

__global__ void splitT_all_kernel(
    const float* __restrict__ Wq, const float* __restrict__ Wk,
    const float* __restrict__ Wv, const float* __restrict__ Wo,
    __half* __restrict__ WqTh, __half* __restrict__ WqTl,
    __half* __restrict__ WkTh, __half* __restrict__ WkTl,
    __half* __restrict__ WvTh, __half* __restrict__ WvTl,
    __half* __restrict__ WoTh, __half* __restrict__ WoTl)
{
    __shared__ float t[32][33];
    const int tx = threadIdx.x, ty = threadIdx.y;
    int id = blockIdx.x;
    if (id < 256) {
        int n0 = (id & 15) * 32, k0 = (id >> 4) * 32;
        splitT_tile(Wq, WqTh, WqTl, DQ, INNER, QSCALE, n0, k0, tx, ty, t);
    } else if (id < 640) {
        id -= 256;
        int n0 = (id & 15) * 32, k0 = (id >> 4) * 32;
        splitT_tile(Wk, WkTh, WkTl, DC, INNER, 1.0f, n0, k0, tx, ty, t);
    } else if (id < 1024) {
        id -= 640;
        int n0 = (id & 15) * 32, k0 = (id >> 4) * 32;
        splitT_tile(Wv, WvTh, WvTl, DC, INNER, 1.0f, n0, k0, tx, ty, t);
    } else {
        id -= 1024;
        int n0 = (id & 15) * 32, k0 = (id >> 4) * 32;
        splitT_tile(Wo, WoTh, WoTl, INNER, DQ, 1.0f, n0, k0, tx, ty, t);
    }
}

// ---------------------------------------------------------------------------
// HMMA fp16 2-product GEMM (unchanged from R13 measured kernel).
// ---------------------------------------------------------------------------
#define GROW 20   // words per smem row (32 fp16 = 16 words + 4 pad)

#define MMA_F16(d, a, b0, b1) \
    asm volatile("mma.sync.aligned.m16n8k16.row.col.f32.f16.f16.f32 " \
        "{%0,%1,%2,%3}, {%4,%5,%6,%7}, {%8,%9}, {%0,%1,%2,%3};" \
        : "+f"((d)[0]), "+f"((d)[1]), "+f"((d)[2]), "+f"((d)[3]) \
        : "r"((a)[0]), "r"((a)[1]), "r"((a)[2]), "r"((a)[3]), \
          "r"(b0), "r"(b1))

template <int MODE>
__global__ __launch_bounds__(256, 2) void hgemm_kernel(
    const float* __restrict__ A,
    const __half* __restrict__ Bh, const __half* __restrict__ Bl,
    const float* __restrict__ bias, float* __restrict__ C,
    __half* __restrict__ Ch, __half* __restrict__ Cl,
    int M, int K, int N)
{
    __shared__ __align__(16) uint32_t sA [128 * GROW];
    __shared__ __align__(16) uint32_t sBh[64 * GROW];
    __shared__ __align__(16) uint32_t sBl[64 * GROW];

    const int tid  = threadIdx.x;
    const int lane = tid & 31, wid = tid >> 5;
    const int wm = (wid >> 1) * 32;     // warp m base: 0,32,64,96
    const int wn = (wid & 1) * 32;      // warp n base: 0 or 32
    const int g  = lane >> 2, tg = lane & 3;
    const int m0 = blockIdx.y * 128, n0 = blockIdx.x * 64;

    const int nch = K >> 5;

    float4 pa[4];
    uint4  pbh, pbl;

    // prefetch chunk 0
    {
        #pragma unroll
        for (int i = 0; i < 4; i++) {
            int id = tid + i * 256;
            int r = id >> 3, c4 = id & 7;
            pa[i] = *reinterpret_cast<const float4*>(A + (size_t)(m0 + r) * K + c4 * 4);
        }
        int r = tid >> 2, gg = tid & 3;
        pbh = *reinterpret_cast<const uint4*>(Bh + (size_t)(n0 + r) * K + gg * 8);
        pbl = *reinterpret_cast<const uint4*>(Bl + (size_t)(n0 + r) * K + gg * 8);
    }

    float acc[2][4][4] = {};   // [mt][nt][reg]

    for (int c = 0; c < nch; c++) {
        #pragma unroll
        for (int i = 0; i < 4; i++) {
            int id = tid + i * 256;
            int r = id >> 3, c4 = id & 7;
            __half2 h0 = __floats2half2_rn(pa[i].x, pa[i].y);
            __half2 h1 = __floats2half2_rn(pa[i].z, pa[i].w);
            int w = r * GROW + c4 * 2;
            sA[w]     = *reinterpret_cast<uint32_t*>(&h0);
            sA[w + 1] = *reinterpret_cast<uint32_t*>(&h1);
        }
        {
            int r = tid >> 2, gg = tid & 3;
            *reinterpret_cast<uint4*>(&sBh[r * GROW + gg * 4]) = pbh;
            *reinterpret_cast<uint4*>(&sBl[r * GROW + gg * 4]) = pbl;
        }
        __syncthreads();

        if (c + 1 < nch) {
            const int k0 = (c + 1) << 5;
            #pragma unroll
            for (int i = 0; i < 4; i++) {
                int id = tid + i * 256;
                int r = id >> 3, c4 = id & 7;
                pa[i] = *reinterpret_cast<const float4*>(A + (size_t)(m0 + r) * K + k0 + c4 * 4);
            }
            int r = tid >> 2, gg = tid & 3;
            pbh = *reinterpret_cast<const uint4*>(Bh + (size_t)(n0 + r) * K + k0 + gg * 8);
            pbl = *reinterpret_cast<const uint4*>(Bl + (size_t)(n0 + r) * K + k0 + gg * 8);
        }

        #pragma unroll
        for (int ks = 0; ks < 2; ks++) {
            uint32_t ah[2][4];
            #pragma unroll
            for (int mt = 0; mt < 2; mt++) {
                int w0 = (wm + mt * 16 + g) * GROW + ks * 8 + tg;
                ah[mt][0] = sA[w0];
                ah[mt][1] = sA[w0 + 8 * GROW];
                ah[mt][2] = sA[w0 + 4];
                ah[mt][3] = sA[w0 + 8 * GROW + 4];
            }
            #pragma unroll
            for (int nt = 0; nt < 4; nt++) {
                int w0 = (wn + nt * 8 + g) * GROW + ks * 8 + tg;
                uint32_t bh0 = sBh[w0], bh1 = sBh[w0 + 4];
                uint32_t bl0 = sBl[w0], bl1 = sBl[w0 + 4];
                #pragma unroll
                for (int mt = 0; mt < 2; mt++) {
                    MMA_F16(acc[mt][nt], ah[mt], bh0, bh1);
                    MMA_F16(acc[mt][nt], ah[mt], bl0, bl1);
                }
            }
        }
        __syncthreads();
    }

    // ---- epilogue
    #pragma unroll
    for (int mt = 0; mt < 2; mt++) {
        const int r = m0 + wm + mt * 16 + g;
        #pragma unroll
        for (int nt = 0; nt < 4; nt++) {
            const int cc = n0 + wn + nt * 8 + tg * 2;
            if (MODE == 0) {
                float2 v0 = make_float2(acc[mt][nt][0], acc[mt][nt][1]);
                float2 v1 = make_float2(acc[mt][nt][2], acc[mt][nt][3]);
                if (bias) {
                    float b0 = bias[cc], b1 = bias[cc + 1];
                    v0.x += b0; v0.y += b1;
                    v1.x += b0; v1.y += b1;
                }
                *reinterpret_cast<float2*>(C + (size_t)r * N + cc)       = v0;
                *reinterpret_cast<float2*>(C + (size_t)(r + 8) * N + cc) = v1;
            } else if (MODE == 1) {        // Q: single fp16
                #pragma unroll
                for (int rr = 0; rr < 2; rr++) {
                    __half2 h = __floats2half2_rn(acc[mt][nt][rr * 2], acc[mt][nt][rr * 2 + 1]);
                    size_t idx = (size_t)(r + rr * 8) * N + cc;
                    *reinterpret_cast<uint32_t*>(Ch + idx) = *reinterpret_cast<uint32_t*>(&h);
                }
            } else if (MODE == 2) {        // K: fp16 hi/lo
                #pragma unroll
                for (int rr = 0; rr < 2; rr++) {
                    float v0 = acc[mt][nt][rr * 2], v1 = acc[mt][nt][rr * 2 + 1];
                    __half2 h = __floats2half2_rn(v0, v1);
                    float2 hf = __half22float2(h);
                    __half2 l = __floats2half2_rn(v0 - hf.x, v1 - hf.y);
                    size_t idx = (size_t)(r + rr * 8) * N + cc;
                    *reinterpret_cast<uint32_t*>(Ch + idx) = *reinterpret_cast<uint32_t*>(&h);
                    *reinterpret_cast<uint32_t*>(Cl + idx) = *reinterpret_cast<uint32_t*>(&l);
                }
            } else {   // MODE 3: V transposed fp16 hi/lo  Vt[b][col][key]
                #pragma unroll
                for (int rr = 0; rr < 2; rr++) {
                    int rg = r + rr * 8;
                    int bb = rg >> 10, key = rg & (NKK - 1);
                    #pragma unroll
                    for (int jc = 0; jc < 2; jc++) {
                        float v = acc[mt][nt][rr * 2 + jc];
                        __half h = __float2half_rn(v);
                        size_t idx = ((size_t)bb * INNER + cc + jc) * NKK + key;
                        Ch[idx] = h;
                        Cl[idx] = __float2half_rn(v - __half2float(h));
                    }
                }
            }
        }
    }
}

// ---------------------------------------------------------------------------
// HMMA flash attention, cp.async double-buffered kv tiles of 64.
// CTA = 128 q x one (b,h); 8 warps x 16 q rows. fp16 2-product split.
// ---------------------------------------------------------------------------
__device__ __forceinline__ float fast_exp2(float y) {
    y = fmaxf(y, -120.0f);
    float n = rintf(y);
    float f = y - n;
    float p = 1.3333558146e-3f;
    p = fmaf(p, f, 9.6181291076e-3f);
    p = fmaf(p, f, 5.5504108665e-2f);
    p = fmaf(p, f, 2.4022650696e-1f);
    p = fmaf(p, f, 6.9314718056e-1f);
    p = fmaf(p, f, 1.0f);
    return p * __int_as_float(((int)n + 127) << 23);
}

#define CP16(dst, src) \
    asm volatile("cp.async.cg.shared.global [%0], [%1], 16;" :: "r"(dst), "l"(src))

// smem word layout: Q 128x36; then 2 buffers of {KH,KL,VH,VL} each 64x36
#define AQW    0
#define BUF_W  9216                         // words per buffer (4 * 2304)
#define BUF0_W 4608
#define KH_OFF 0
#define KL_OFF 2304
#define VH_OFF 4608
#define VL_OFF 6912
#define ATT_WORDS (4608 + 2 * BUF_W)        // 23040
#define ATT_BYTES (ATT_WORDS * 4)           // 92160 B

__device__ __forceinline__ void attn_prefetch(
    uint32_t swa, int tid, int kt, uint32_t bufw,
    const __half* __restrict__ Kh_, const __half* __restrict__ Kl_,
    const __half* __restrict__ Vh_, const __half* __restrict__ Vl_,
    int b, int h)
{
    #pragma unroll
    for (int i = 0; i < 2; i++) {
        int id = tid + i * 256;
        int r = id >> 3, u = id & 7;
        size_t koff = ((size_t)(b * NKK + kt * 64 + r)) * INNER + h * 64 + u * 8;
        size_t voff = ((size_t)(b * INNER + h * 64 + r)) * NKK + kt * 64 + u * 8;
        uint32_t dbase = swa + (bufw + r * 36 + u * 4) * 4;
        CP16(dbase + KH_OFF * 4, Kh_ + koff);
        CP16(dbase + KL_OFF * 4, Kl_ + koff);
        CP16(dbase + VH_OFF * 4, Vh_ + voff);
        CP16(dbase + VL_OFF * 4, Vl_ + voff);
    }
}

__global__ __launch_bounds__(256, 2) void attn_mma_kernel(
    const __half* __restrict__ Qh_,
    const __half* __restrict__ Kh_, const __half* __restrict__ Kl_,
    const __half* __restrict__ Vh_, const __half* __restrict__ Vl_,
    float* __restrict__ AO)
{
    extern __shared__ uint32_t sw[];
    const uint32_t swa = (uint32_t)__cvta_generic_to_shared(sw);
    const int tid = threadIdx.x, lane = tid & 31, w = tid >> 5;
    const int g = lane >> 2, tg = lane & 3;
    const int q0 = blockIdx.x * 128;
    const int bh = blockIdx.y, b = bh >> 3, h = bh & 7;

    // ---- kick off prefetch of kv tile 0 into buffer 0
    attn_prefetch(swa, tid, 0, BUF0_W, Kh_, Kl_, Vh_, Vl_, b, h);
    asm volatile("cp.async.commit_group;");

    // ---- load Q tile [128 q][64 d] (single fp16) while tile 0 streams
    {
        const __half* sq = Qh_ + ((size_t)(b * NQ + q0)) * INNER + h * 64;
        #pragma unroll
        for (int i = 0; i < 4; i++) {
            int id = tid + i * 256;
            int r = id >> 3, u = id & 7;
            uint4 v = *reinterpret_cast<const uint4*>(sq + (size_t)r * INNER + u * 8);
            *reinterpret_cast<uint4*>(&sw[AQW + r * 36 + u * 4]) = v;
        }
    }

    float o[8][4] = {};
    float m0 = -1e30f, m1 = -1e30f, l0 = 0.0f, l1 = 0.0f;

    #pragma unroll 1
    for (int kt = 0; kt < NKK / 64; kt++) {
        const uint32_t W = BUF0_W + (kt & 1) * BUF_W;

        // prefetch next tile into the other buffer (safe: its readers finished
        // at the __syncthreads() ending iteration kt-1)
        if (kt + 1 < NKK / 64) {
            attn_prefetch(swa, tid, kt + 1, BUF0_W + ((kt + 1) & 1) * BUF_W,
                          Kh_, Kl_, Vh_, Vl_, b, h);
            asm volatile("cp.async.commit_group;");
            asm volatile("cp.async.wait_group 1;");
        } else {
            asm volatile("cp.async.wait_group 0;");
        }
        __syncthreads();                 // this tile's data visible to all warps

        // ---- S = Q K^T (2 products), warp: 16 q x 64 keys
        float acc[8][4] = {};
        #pragma unroll
        for (int ks = 0; ks < 4; ks++) {
            int wq = AQW + (w * 16 + g) * 36 + ks * 8 + tg;
            uint32_t qh[4] = { sw[wq], sw[wq + 8 * 36],
                               sw[wq + 4], sw[wq + 8 * 36 + 4] };
            #pragma unroll
            for (int nt = 0; nt < 8; nt++) {
                int wk = W + KH_OFF + (nt * 8 + g) * 36 + ks * 8 + tg;
                int wl = W + KL_OFF + (nt * 8 + g) * 36 + ks * 8 + tg;
                uint32_t bh0 = sw[wk], bh1 = sw[wk + 4];
                uint32_t bl0 = sw[wl], bl1 = sw[wl + 4];
                MMA_F16(acc[nt], qh, bh0, bh1);
                MMA_F16(acc[nt], qh, bl0, bl1);
            }
        }

        // ---- register online softmax in exp2 domain (rows g and g+8)
        float tm0 = -1e30f, tm1 = -1e30f;
        #pragma unroll
        for (int nt = 0; nt < 8; nt++) {
            tm0 = fmaxf(tm0, fmaxf(acc[nt][0], acc[nt][1]));
            tm1 = fmaxf(tm1, fmaxf(acc[nt][2], acc[nt][3]));
        }
        tm0 = fmaxf(tm0, __shfl_xor_sync(0xffffffffu, tm0, 1));
        tm0 = fmaxf(tm0, __shfl_xor_sync(0xffffffffu, tm0, 2));
        tm1 = fmaxf(tm1, __shfl_xor_sync(0xffffffffu, tm1, 1));
        tm1 = fmaxf(tm1, __shfl_xor_sync(0xffffffffu, tm1, 2));
        float mn0 = fmaxf(m0, tm0), mn1 = fmaxf(m1, tm1);
        float r0 = fast_exp2(m0 - mn0), r1 = fast_exp2(m1 - mn1);
        m0 = mn0; m1 = mn1;
        float s0 = 0.0f, s1 = 0.0f;
        #pragma unroll
        for (int nt = 0; nt < 8; nt++) {
            acc[nt][0] = fast_exp2(acc[nt][0] - mn0); s0 += acc[nt][0];
            acc[nt][1] = fast_exp2(acc[nt][1] - mn0); s0 += acc[nt][1];
            acc[nt][2] = fast_exp2(acc[nt][2] - mn1); s1 += acc[nt][2];
            acc[nt][3] = fast_exp2(acc[nt][3] - mn1); s1 += acc[nt][3];
        }
        s0 += __shfl_xor_sync(0xffffffffu, s0, 1);
        s0 += __shfl_xor_sync(0xffffffffu, s0, 2);
        s1 += __shfl_xor_sync(0xffffffffu, s1, 1);
        s1 += __shfl_xor_sync(0xffffffffu, s1, 2);
        l0 = l0 * r0 + s0;
        l1 = l1 * r1 + s1;
        #pragma unroll
        for (int nt = 0; nt < 8; nt++) {
            o[nt][0] *= r0; o[nt][1] *= r0;
            o[nt][2] *= r1; o[nt][3] *= r1;
        }

        // ---- O += P V (P single fp16; 2 products)
        #pragma unroll
        for (int ks = 0; ks < 4; ks++) {
            uint32_t ah[4];
            {
                __half2 t;
                t = __floats2half2_rn(acc[2 * ks][0],     acc[2 * ks][1]);
                ah[0] = *reinterpret_cast<uint32_t*>(&t);
                t = __floats2half2_rn(acc[2 * ks][2],     acc[2 * ks][3]);
                ah[1] = *reinterpret_cast<uint32_t*>(&t);
                t = __floats2half2_rn(acc[2 * ks + 1][0], acc[2 * ks + 1][1]);
                ah[2] = *reinterpret_cast<uint32_t*>(&t);
                t = __floats2half2_rn(acc[2 * ks + 1][2], acc[2 * ks + 1][3]);
                ah[3] = *reinterpret_cast<uint32_t*>(&t);
            }
            #pragma unroll
            for (int nt = 0; nt < 8; nt++) {
                int wv = W + VH_OFF + (nt * 8 + g) * 36 + ks * 8 + tg;
                int wl = W + VL_OFF + (nt * 8 + g) * 36 + ks * 8 + tg;
                uint32_t bh0 = sw[wv], bh1 = sw[wv + 4];
                uint32_t bl0 = sw[wl], bl1 = sw[wl + 4];
                MMA_F16(o[nt], ah, bh0, bh1);
                MMA_F16(o[nt], ah, bl0, bl1);
            }
        }
        __syncthreads();                 // all warps done with this buffer
    }

    // ---- epilogue: normalize, store fp32 AO
    float i0 = 1.0f / l0, i1 = 1.0f / l1;
    const int rg = q0 + w * 16 + g;
    #pragma unroll
    for (int nt = 0; nt < 8; nt++) {
        const int col = h * 64 + nt * 8 + tg * 2;
        float2 v0 = make_float2(o[nt][0] * i0, o[nt][1] * i0);
        float2 v1 = make_float2(o[nt][2] * i1, o[nt][3] * i1);
        *reinterpret_cast<float2*>(AO + (size_t)(b * NQ + rg) * INNER + col)     = v0;
        *reinterpret_cast<float2*>(AO + (size_t)(b * NQ + rg + 8) * INNER + col) = v1;
    }
}

// ---------------------------------------------------------------------------
// Launcher
// ---------------------------------------------------------------------------
extern "C" void kernel_launch(void* const* d_in, const int* in_sizes, int n_in,
                              void* d_out, int out_size)
{
    const float* x   = (const float*)d_in[0];  // [4,2048,512]
    const float* ctx = (const float*)d_in[1];  // [4,1024,768]
    const float* Wq  = (const float*)d_in[2];  // [512,512]
    const float* Wk  = (const float*)d_in[3];  // [768,512]
    const float* Wv  = (const float*)d_in[4];  // [768,512]
    const float* Wo  = (const float*)d_in[5];  // [512,512]
    const float* bo  = (const float*)d_in[6];  // [512]
    float* out = (float*)d_out;

    float* AOb;
    cudaGetSymbolAddress((void**)&AOb, g_AO);

    __half *Qh, *Kh, *Kl, *Vth, *Vtl;
    cudaGetSymbolAddress((void**)&Qh,  g_Qh);
    cudaGetSymbolAddress((void**)&Kh,  g_Kh);   cudaGetSymbolAddress((void**)&Kl,  g_Kl);
    cudaGetSymbolAddress((void**)&Vth, g_Vth);  cudaGetSymbolAddress((void**)&Vtl, g_Vtl);

    __half *WqTh, *WqTl, *WkTh, *WkTl, *WvTh, *WvTl, *WoTh, *WoTl;
    cudaGetSymbolAddress((void**)&WqTh, g_WqTh); cudaGetSymbolAddress((void**)&WqTl, g_WqTl);
    cudaGetSymbolAddress((void**)&WkTh, g_WkTh); cudaGetSymbolAddress((void**)&WkTl, g_WkTl);
    cudaGetSymbolAddress((void**)&WvTh, g_WvTh); cudaGetSymbolAddress((void**)&WvTl, g_WvTl);
    cudaGetSymbolAddress((void**)&WoTh, g_WoTh); cudaGetSymbolAddress((void**)&WoTl, g_WoTl);

    cudaFuncSetAttribute(attn_mma_kernel,
                         cudaFuncAttributeMaxDynamicSharedMemorySize, ATT_BYTES);

    // --- all weight transposes + hi/lo splits in one launch ---
    splitT_all_kernel<<<1280, dim3(32, 8)>>>(
        Wq, Wk, Wv, Wo, WqTh, WqTl, WkTh, WkTl, WvTh, WvTl, WoTh, WoTl);

    // --- projections (epilogues emit fp16 operands for attention) ---
    hgemm_kernel<1><<<dim3(INNER / 64, (NB * NQ) / 128), 256>>>(
        x, WqTh, WqTl, nullptr, nullptr, Qh, nullptr, NB * NQ, DQ, INNER);
    hgemm_kernel<2><<<dim3(INNER / 64, (NB * NKK) / 128), 256>>>(
        ctx, WkTh, WkTl, nullptr, nullptr, Kh, Kl, NB * NKK, DC, INNER);
    hgemm_kernel<3><<<dim3(INNER / 64, (NB * NKK) / 128), 256>>>(
        ctx, WvTh, WvTl, nullptr, nullptr, Vth, Vtl, NB * NKK, DC, INNER);

    // --- fused attention on tensor cores (fp16, 2-product, cp.async) ---
    attn_mma_kernel<<<dim3(NQ / 128, NB * NHEAD), 256, ATT_BYTES>>>(
        Qh, Kh, Kl, Vth, Vtl, AOb);

    // --- output projection (+bias) ---
    hgemm_kernel<0><<<dim3(DQ / 64, (NB * NQ) / 128), 256>>>(
        AOb, WoTh, WoTl, bo, out, nullptr, nullptr, NB * NQ, INNER, DQ);
}

// round 16
// speedup vs baseline: 4.6000x; 1.1157x over previous
#include <cuda_runtime.h>
#include <cuda_fp16.h>
#include <cstdint>
#include <cstddef>

// Problem constants
#define NB    4
#define NQ    2048
#define DQ    512
#define NKK   1024
#define DC    768
#define NHEAD 8
#define DHEAD 64
#define INNER 512   // NHEAD*DHEAD

// log2(e) * DIM_HEAD^-0.5  (folded into Wq so softmax runs in exp2 domain)
#define QSCALE 0.1803368801111204f

// ---------------------------------------------------------------------------
// Scratch (device globals — no allocation allowed)
// ---------------------------------------------------------------------------
// fp16 activations
__device__ __half g_x16 [NB * NQ  * DQ];
__device__ __half g_c16 [NB * NKK * DC];
__device__ __half g_AO16[NB * NQ  * INNER];

// attention operands produced by projection GEMM epilogues (fp16)
__device__ __half g_Qh [NB * NQ  * INNER];                          // single
__device__ __half g_Kh [NB * NKK * INNER], g_Kl [NB * NKK * INNER]; // hi/lo
__device__ __half g_Vth[NB * INNER * NKK];                          // single, [b][hd][key]

// transposed + split weights (fp16 hi/lo): WT[n][k] = W[k][n]
__device__ __half g_WqTh[INNER * DQ],  g_WqTl[INNER * DQ];
__device__ __half g_WkTh[INNER * DC],  g_WkTl[INNER * DC];
__device__ __half g_WvTh[INNER * DC],  g_WvTl[INNER * DC];
__device__ __half g_WoTh[DQ * INNER],  g_WoTl[DQ * INNER];

// ---------------------------------------------------------------------------
// fp32 -> fp16 convert (4 elems/thread)
// ---------------------------------------------------------------------------
__global__ void cvt16_kernel(const float* __restrict__ in,
                             __half* __restrict__ out, int n4)
{
    int i = blockIdx.x * blockDim.x + threadIdx.x;
    if (i < n4) {
        float4 v = reinterpret_cast<const float4*>(in)[i];
        __half2 h0 = __floats2half2_rn(v.x, v.y);
        __half2 h1 = __floats2half2_rn(v.z, v.w);
        uint2 o;
        o.x = *reinterpret_cast<uint32_t*>(&h0);
        o.y = *reinterpret_cast<uint32_t*>(&h1);
        reinterpret_cast<uint2*>(out)[i] = o;
    }
}

// ---------------------------------------------------------------------------
// Batched transpose + split for all 4 weights in one launch.
// ---------------------------------------------------------------------------
__device__ __forceinline__ void splitT_tile(
    const float* __restrict__ W, __half* __restrict__ hT,
    __half* __restrict__ lT, int K, int N, float scale,
    int n0, int k0, int tx, int ty, float (*t)[33])
{
    #pragma unroll
    for (int r = ty; r < 32; r += 8)
        t[r][tx] = W[(size_t)(k0 + r) * N + n0 + tx];
    __syncthreads();
    #pragma unroll
    for (int r = ty; r < 32; r += 8) {
        float v = t[tx][r] * scale;       // element (n = n0+r, k = k0+tx)
        __half h = __float2half_rn(v);
        size_t idx = (size_t)(n0 + r) * K + k0 + tx;
        hT[idx] = h;
        lT[idx] = __float2half_rn(v - __half2float(h));
    }
}

__global__ void splitT_all_kernel(
    const float* __restrict__ Wq, const float* __restrict__ Wk,
    const float* __restrict__ Wv, const float* __restrict__ Wo,
    __half* __restrict__ WqTh, __half* __restrict__ WqTl,
    __half* __restrict__ WkTh, __half* __restrict__ WkTl,
    __half* __restrict__ WvTh, __half* __restrict__ WvTl,
    __half* __restrict__ WoTh, __half* __restrict__ WoTl)
{
    __shared__ float t[32][33];
    const int tx = threadIdx.x, ty = threadIdx.y;
    int id = blockIdx.x;
    if (id < 256) {
        int n0 = (id & 15) * 32, k0 = (id >> 4) * 32;
        splitT_tile(Wq, WqTh, WqTl, DQ, INNER, QSCALE, n0, k0, tx, ty, t);
    } else if (id < 640) {
        id -= 256;
        int n0 = (id & 15) * 32, k0 = (id >> 4) * 32;
        splitT_tile(Wk, WkTh, WkTl, DC, INNER, 1.0f, n0, k0, tx, ty, t);
    } else if (id < 1024) {
        id -= 640;
        int n0 = (id & 15) * 32, k0 = (id >> 4) * 32;
        splitT_tile(Wv, WvTh, WvTl, DC, INNER, 1.0f, n0, k0, tx, ty, t);
    } else {
        id -= 1024;
        int n0 = (id & 15) * 32, k0 = (id >> 4) * 32;
        splitT_tile(Wo, WoTh, WoTl, INNER, DQ, 1.0f, n0, k0, tx, ty, t);
    }
}

// ---------------------------------------------------------------------------
// HMMA fp16 2-product GEMM, cp.async double-buffered.
// A fp16 [M,K]; B [N,K] fp16 hi/lo. 128x64 CTA tile, BK=32, 8 warps (4m x 2n),
// warp tile 32x32, m16n8k16, fp32 accum. 3 CTAs/SM target.
// Epilogue MODE: 0 = fp32 C (+bias); 1 = fp16 single (Q);
//                2 = fp16 hi/lo natural (K); 3 = fp16 single transposed-V.
// ---------------------------------------------------------------------------
#define GROW 20   // words per smem row (32 fp16 = 16 words + 4 pad)

#define MMA_F16(d, a, b0, b1) \
    asm volatile("mma.sync.aligned.m16n8k16.row.col.f32.f16.f16.f32 " \
        "{%0,%1,%2,%3}, {%4,%5,%6,%7}, {%8,%9}, {%0,%1,%2,%3};" \
        : "+f"((d)[0]), "+f"((d)[1]), "+f"((d)[2]), "+f"((d)[3]) \
        : "r"((a)[0]), "r"((a)[1]), "r"((a)[2]), "r"((a)[3]), \
          "r"(b0), "r"(b1))

#define CP16(dst, src) \
    asm volatile("cp.async.cg.shared.global [%0], [%1], 16;" :: "r"(dst), "l"(src))

// per-buffer word layout: A at +0 (128*20), Bh at +2560 (64*20), Bl at +3840
#define GB_BUF_W 5120

__device__ __forceinline__ void gemm_prefetch(
    uint32_t swa, int tid, int c, uint32_t base,
    const __half* __restrict__ A, const __half* __restrict__ Bh,
    const __half* __restrict__ Bl, int m0, int n0, int K)
{
    const int k0 = c << 5;
    #pragma unroll
    for (int i = 0; i < 2; i++) {
        int id = tid + i * 256;
        int r = id >> 2, u = id & 3;
        CP16(swa + (base + r * GROW + u * 4) * 4,
             A + (size_t)(m0 + r) * K + k0 + u * 8);
    }
    {
        int r = tid >> 2, u = tid & 3;
        CP16(swa + (base + 2560 + r * GROW + u * 4) * 4,
             Bh + (size_t)(n0 + r) * K + k0 + u * 8);
        CP16(swa + (base + 3840 + r * GROW + u * 4) * 4,
             Bl + (size_t)(n0 + r) * K + k0 + u * 8);
    }
}

template <int MODE>
__global__ __launch_bounds__(256, 3) void hgemm_kernel(
    const __half* __restrict__ A,
    const __half* __restrict__ Bh, const __half* __restrict__ Bl,
    const float* __restrict__ bias, float* __restrict__ C,
    __half* __restrict__ Ch, __half* __restrict__ Cl,
    int M, int K, int N)
{
    __shared__ __align__(16) uint32_t sm[2 * GB_BUF_W];
    const uint32_t swa = (uint32_t)__cvta_generic_to_shared(sm);

    const int tid  = threadIdx.x;
    const int lane = tid & 31, wid = tid >> 5;
    const int wm = (wid >> 1) * 32;     // warp m base: 0,32,64,96
    const int wn = (wid & 1) * 32;      // warp n base: 0 or 32
    const int g  = lane >> 2, tg = lane & 3;
    const int m0 = blockIdx.y * 128, n0 = blockIdx.x * 64;

    const int nch = K >> 5;

    gemm_prefetch(swa, tid, 0, 0, A, Bh, Bl, m0, n0, K);
    asm volatile("cp.async.commit_group;");

    float acc[2][4][4] = {};   // [mt][nt][reg]

    #pragma unroll 1
    for (int c = 0; c < nch; c++) {
        const uint32_t W = (c & 1) * GB_BUF_W;

        if (c + 1 < nch) {
            gemm_prefetch(swa, tid, c + 1, ((c + 1) & 1) * GB_BUF_W,
                          A, Bh, Bl, m0, n0, K);
            asm volatile("cp.async.commit_group;");
            asm volatile("cp.async.wait_group 1;");
        } else {
            asm volatile("cp.async.wait_group 0;");
        }
        __syncthreads();

        #pragma unroll
        for (int ks = 0; ks < 2; ks++) {
            uint32_t ah[2][4];
            #pragma unroll
            for (int mt = 0; mt < 2; mt++) {
                int w0 = W + (wm + mt * 16 + g) * GROW + ks * 8 + tg;
                ah[mt][0] = sm[w0];
                ah[mt][1] = sm[w0 + 8 * GROW];
                ah[mt][2] = sm[w0 + 4];
                ah[mt][3] = sm[w0 + 8 * GROW + 4];
            }
            #pragma unroll
            for (int nt = 0; nt < 4; nt++) {
                int wb = W + 2560 + (wn + nt * 8 + g) * GROW + ks * 8 + tg;
                int wl = wb + 1280;
                uint32_t bh0 = sm[wb], bh1 = sm[wb + 4];
                uint32_t bl0 = sm[wl], bl1 = sm[wl + 4];
                #pragma unroll
                for (int mt = 0; mt < 2; mt++) {
                    MMA_F16(acc[mt][nt], ah[mt], bh0, bh1);
                    MMA_F16(acc[mt][nt], ah[mt], bl0, bl1);
                }
            }
        }
        __syncthreads();                 // readers done before next prefetch hits this buffer
    }

    // ---- epilogue
    #pragma unroll
    for (int mt = 0; mt < 2; mt++) {
        const int r = m0 + wm + mt * 16 + g;
        #pragma unroll
        for (int nt = 0; nt < 4; nt++) {
            const int cc = n0 + wn + nt * 8 + tg * 2;
            if (MODE == 0) {
                float2 v0 = make_float2(acc[mt][nt][0], acc[mt][nt][1]);
                float2 v1 = make_float2(acc[mt][nt][2], acc[mt][nt][3]);
                if (bias) {
                    float b0 = bias[cc], b1 = bias[cc + 1];
                    v0.x += b0; v0.y += b1;
                    v1.x += b0; v1.y += b1;
                }
                *reinterpret_cast<float2*>(C + (size_t)r * N + cc)       = v0;
                *reinterpret_cast<float2*>(C + (size_t)(r + 8) * N + cc) = v1;
            } else if (MODE == 1) {        // Q: single fp16
                #pragma unroll
                for (int rr = 0; rr < 2; rr++) {
                    __half2 h = __floats2half2_rn(acc[mt][nt][rr * 2], acc[mt][nt][rr * 2 + 1]);
                    size_t idx = (size_t)(r + rr * 8) * N + cc;
                    *reinterpret_cast<uint32_t*>(Ch + idx) = *reinterpret_cast<uint32_t*>(&h);
                }
            } else if (MODE == 2) {        // K: fp16 hi/lo
                #pragma unroll
                for (int rr = 0; rr < 2; rr++) {
                    float v0 = acc[mt][nt][rr * 2], v1 = acc[mt][nt][rr * 2 + 1];
                    __half2 h = __floats2half2_rn(v0, v1);
                    float2 hf = __half22float2(h);
                    __half2 l = __floats2half2_rn(v0 - hf.x, v1 - hf.y);
                    size_t idx = (size_t)(r + rr * 8) * N + cc;
                    *reinterpret_cast<uint32_t*>(Ch + idx) = *reinterpret_cast<uint32_t*>(&h);
                    *reinterpret_cast<uint32_t*>(Cl + idx) = *reinterpret_cast<uint32_t*>(&l);
                }
            } else {   // MODE 3: V transposed single fp16  Vt[b][col][key]
                #pragma unroll
                for (int rr = 0; rr < 2; rr++) {
                    int rg = r + rr * 8;
                    int bb = rg >> 10, key = rg & (NKK - 1);
                    #pragma unroll
                    for (int jc = 0; jc < 2; jc++) {
                        size_t idx = ((size_t)bb * INNER + cc + jc) * NKK + key;
                        Ch[idx] = __float2half_rn(acc[mt][nt][rr * 2 + jc]);
                    }
                }
            }
        }
    }
}

// ---------------------------------------------------------------------------
// HMMA flash attention, cp.async double-buffered kv tiles of 64.
// CTA = 128 q x one (b,h); 8 warps x 16 q rows.
// QK: 2 products (Qh*Kh + Qh*Kl). PV: 1 product (P*Vh). AO written fp16.
// ---------------------------------------------------------------------------
__device__ __forceinline__ float fast_exp2(float y) {
    y = fmaxf(y, -120.0f);
    float n = rintf(y);
    float f = y - n;
    float p = 1.3333558146e-3f;
    p = fmaf(p, f, 9.6181291076e-3f);
    p = fmaf(p, f, 5.5504108665e-2f);
    p = fmaf(p, f, 2.4022650696e-1f);
    p = fmaf(p, f, 6.9314718056e-1f);
    p = fmaf(p, f, 1.0f);
    return p * __int_as_float(((int)n + 127) << 23);
}

// smem word layout: Q 128x36; then 2 buffers of {KH,KL,VH} each 64x36
#define AQW    0
#define AT_BUF_W  6912                      // words per buffer (3 * 2304)
#define AT_BUF0_W 4608
#define KH_OFF 0
#define KL_OFF 2304
#define VH_OFF 4608
#define ATT_WORDS (4608 + 2 * AT_BUF_W)     // 18432
#define ATT_BYTES (ATT_WORDS * 4)           // 73728 B

__device__ __forceinline__ void attn_prefetch(
    uint32_t swa, int tid, int kt, uint32_t bufw,
    const __half* __restrict__ Kh_, const __half* __restrict__ Kl_,
    const __half* __restrict__ Vh_, int b, int h)
{
    #pragma unroll
    for (int i = 0; i < 2; i++) {
        int id = tid + i * 256;
        int r = id >> 3, u = id & 7;
        size_t koff = ((size_t)(b * NKK + kt * 64 + r)) * INNER + h * 64 + u * 8;
        size_t voff = ((size_t)(b * INNER + h * 64 + r)) * NKK + kt * 64 + u * 8;
        uint32_t dbase = swa + (bufw + r * 36 + u * 4) * 4;
        CP16(dbase + KH_OFF * 4, Kh_ + koff);
        CP16(dbase + KL_OFF * 4, Kl_ + koff);
        CP16(dbase + VH_OFF * 4, Vh_ + voff);
    }
}

__global__ __launch_bounds__(256, 2) void attn_mma_kernel(
    const __half* __restrict__ Qh_,
    const __half* __restrict__ Kh_, const __half* __restrict__ Kl_,
    const __half* __restrict__ Vh_,
    __half* __restrict__ AO)
{
    extern __shared__ uint32_t sw[];
    const uint32_t swa = (uint32_t)__cvta_generic_to_shared(sw);
    const int tid = threadIdx.x, lane = tid & 31, w = tid >> 5;
    const int g = lane >> 2, tg = lane & 3;
    const int q0 = blockIdx.x * 128;
    const int bh = blockIdx.y, b = bh >> 3, h = bh & 7;

    // ---- kick off prefetch of kv tile 0 into buffer 0
    attn_prefetch(swa, tid, 0, AT_BUF0_W, Kh_, Kl_, Vh_, b, h);
    asm volatile("cp.async.commit_group;");

    // ---- load Q tile [128 q][64 d] (single fp16) while tile 0 streams
    {
        const __half* sq = Qh_ + ((size_t)(b * NQ + q0)) * INNER + h * 64;
        #pragma unroll
        for (int i = 0; i < 4; i++) {
            int id = tid + i * 256;
            int r = id >> 3, u = id & 7;
            uint4 v = *reinterpret_cast<const uint4*>(sq + (size_t)r * INNER + u * 8);
            *reinterpret_cast<uint4*>(&sw[AQW + r * 36 + u * 4]) = v;
        }
    }

    float o[8][4] = {};
    float m0 = -1e30f, m1 = -1e30f, l0 = 0.0f, l1 = 0.0f;

    #pragma unroll 1
    for (int kt = 0; kt < NKK / 64; kt++) {
        const uint32_t W = AT_BUF0_W + (kt & 1) * AT_BUF_W;

        if (kt + 1 < NKK / 64) {
            attn_prefetch(swa, tid, kt + 1, AT_BUF0_W + ((kt + 1) & 1) * AT_BUF_W,
                          Kh_, Kl_, Vh_, b, h);
            asm volatile("cp.async.commit_group;");
            asm volatile("cp.async.wait_group 1;");
        } else {
            asm volatile("cp.async.wait_group 0;");
        }
        __syncthreads();

        // ---- S = Q K^T (2 products), warp: 16 q x 64 keys
        float acc[8][4] = {};
        #pragma unroll
        for (int ks = 0; ks < 4; ks++) {
            int wq = AQW + (w * 16 + g) * 36 + ks * 8 + tg;
            uint32_t qh[4] = { sw[wq], sw[wq + 8 * 36],
                               sw[wq + 4], sw[wq + 8 * 36 + 4] };
            #pragma unroll
            for (int nt = 0; nt < 8; nt++) {
                int wk = W + KH_OFF + (nt * 8 + g) * 36 + ks * 8 + tg;
                int wl = W + KL_OFF + (nt * 8 + g) * 36 + ks * 8 + tg;
                uint32_t bh0 = sw[wk], bh1 = sw[wk + 4];
                uint32_t bl0 = sw[wl], bl1 = sw[wl + 4];
                MMA_F16(acc[nt], qh, bh0, bh1);
                MMA_F16(acc[nt], qh, bl0, bl1);
            }
        }

        // ---- register online softmax in exp2 domain (rows g and g+8)
        float tm0 = -1e30f, tm1 = -1e30f;
        #pragma unroll
        for (int nt = 0; nt < 8; nt++) {
            tm0 = fmaxf(tm0, fmaxf(acc[nt][0], acc[nt][1]));
            tm1 = fmaxf(tm1, fmaxf(acc[nt][2], acc[nt][3]));
        }
        tm0 = fmaxf(tm0, __shfl_xor_sync(0xffffffffu, tm0, 1));
        tm0 = fmaxf(tm0, __shfl_xor_sync(0xffffffffu, tm0, 2));
        tm1 = fmaxf(tm1, __shfl_xor_sync(0xffffffffu, tm1, 1));
        tm1 = fmaxf(tm1, __shfl_xor_sync(0xffffffffu, tm1, 2));
        float mn0 = fmaxf(m0, tm0), mn1 = fmaxf(m1, tm1);
        float r0 = fast_exp2(m0 - mn0), r1 = fast_exp2(m1 - mn1);
        m0 = mn0; m1 = mn1;
        float s0 = 0.0f, s1 = 0.0f;
        #pragma unroll
        for (int nt = 0; nt < 8; nt++) {
            acc[nt][0] = fast_exp2(acc[nt][0] - mn0); s0 += acc[nt][0];
            acc[nt][1] = fast_exp2(acc[nt][1] - mn0); s0 += acc[nt][1];
            acc[nt][2] = fast_exp2(acc[nt][2] - mn1); s1 += acc[nt][2];
            acc[nt][3] = fast_exp2(acc[nt][3] - mn1); s1 += acc[nt][3];
        }
        s0 += __shfl_xor_sync(0xffffffffu, s0, 1);
        s0 += __shfl_xor_sync(0xffffffffu, s0, 2);
        s1 += __shfl_xor_sync(0xffffffffu, s1, 1);
        s1 += __shfl_xor_sync(0xffffffffu, s1, 2);
        l0 = l0 * r0 + s0;
        l1 = l1 * r1 + s1;
        #pragma unroll
        for (int nt = 0; nt < 8; nt++) {
            o[nt][0] *= r0; o[nt][1] *= r0;
            o[nt][2] *= r1; o[nt][3] *= r1;
        }

        // ---- O += P V (P single fp16; 1 product: P*Vh)
        #pragma unroll
        for (int ks = 0; ks < 4; ks++) {
            uint32_t ah[4];
            {
                __half2 t;
                t = __floats2half2_rn(acc[2 * ks][0],     acc[2 * ks][1]);
                ah[0] = *reinterpret_cast<uint32_t*>(&t);
                t = __floats2half2_rn(acc[2 * ks][2],     acc[2 * ks][3]);
                ah[1] = *reinterpret_cast<uint32_t*>(&t);
                t = __floats2half2_rn(acc[2 * ks + 1][0], acc[2 * ks + 1][1]);
                ah[2] = *reinterpret_cast<uint32_t*>(&t);
                t = __floats2half2_rn(acc[2 * ks + 1][2], acc[2 * ks + 1][3]);
                ah[3] = *reinterpret_cast<uint32_t*>(&t);
            }
            #pragma unroll
            for (int nt = 0; nt < 8; nt++) {
                int wv = W + VH_OFF + (nt * 8 + g) * 36 + ks * 8 + tg;
                MMA_F16(o[nt], ah, sw[wv], sw[wv + 4]);
            }
        }
        __syncthreads();                 // all warps done with this buffer
    }

    // ---- epilogue: normalize, store fp16 AO
    float i0 = 1.0f / l0, i1 = 1.0f / l1;
    const int rg = q0 + w * 16 + g;
    #pragma unroll
    for (int nt = 0; nt < 8; nt++) {
        const int col = h * 64 + nt * 8 + tg * 2;
        __half2 v0 = __floats2half2_rn(o[nt][0] * i0, o[nt][1] * i0);
        __half2 v1 = __floats2half2_rn(o[nt][2] * i1, o[nt][3] * i1);
        *reinterpret_cast<uint32_t*>(AO + (size_t)(b * NQ + rg) * INNER + col) =
            *reinterpret_cast<uint32_t*>(&v0);
        *reinterpret_cast<uint32_t*>(AO + (size_t)(b * NQ + rg + 8) * INNER + col) =
            *reinterpret_cast<uint32_t*>(&v1);
    }
}

// ---------------------------------------------------------------------------
// Launcher
// ---------------------------------------------------------------------------
extern "C" void kernel_launch(void* const* d_in, const int* in_sizes, int n_in,
                              void* d_out, int out_size)
{
    const float* x   = (const float*)d_in[0];  // [4,2048,512]
    const float* ctx = (const float*)d_in[1];  // [4,1024,768]
    const float* Wq  = (const float*)d_in[2];  // [512,512]
    const float* Wk  = (const float*)d_in[3];  // [768,512]
    const float* Wv  = (const float*)d_in[4];  // [768,512]
    const float* Wo  = (const float*)d_in[5];  // [512,512]
    const float* bo  = (const float*)d_in[6];  // [512]
    float* out = (float*)d_out;

    __half *x16, *c16, *AO16;
    cudaGetSymbolAddress((void**)&x16,  g_x16);
    cudaGetSymbolAddress((void**)&c16,  g_c16);
    cudaGetSymbolAddress((void**)&AO16, g_AO16);

    __half *Qh, *Kh, *Kl, *Vth;
    cudaGetSymbolAddress((void**)&Qh,  g_Qh);
    cudaGetSymbolAddress((void**)&Kh,  g_Kh);   cudaGetSymbolAddress((void**)&Kl,  g_Kl);
    cudaGetSymbolAddress((void**)&Vth, g_Vth);

    __half *WqTh, *WqTl, *WkTh, *WkTl, *WvTh, *WvTl, *WoTh, *WoTl;
    cudaGetSymbolAddress((void**)&WqTh, g_WqTh); cudaGetSymbolAddress((void**)&WqTl, g_WqTl);
    cudaGetSymbolAddress((void**)&WkTh, g_WkTh); cudaGetSymbolAddress((void**)&WkTl, g_WkTl);
    cudaGetSymbolAddress((void**)&WvTh, g_WvTh); cudaGetSymbolAddress((void**)&WvTl, g_WvTl);
    cudaGetSymbolAddress((void**)&WoTh, g_WoTh); cudaGetSymbolAddress((void**)&WoTl, g_WoTl);

    cudaFuncSetAttribute(attn_mma_kernel,
                         cudaFuncAttributeMaxDynamicSharedMemorySize, ATT_BYTES);

    // --- activation fp32 -> fp16 converts + weight transpose/splits ---
    cvt16_kernel<<<(NB * NQ * DQ / 4 + 255) / 256, 256>>>(x, x16, NB * NQ * DQ / 4);
    cvt16_kernel<<<(NB * NKK * DC / 4 + 255) / 256, 256>>>(ctx, c16, NB * NKK * DC / 4);
    splitT_all_kernel<<<1280, dim3(32, 8)>>>(
        Wq, Wk, Wv, Wo, WqTh, WqTl, WkTh, WkTl, WvTh, WvTl, WoTh, WoTl);

    // --- projections (epilogues emit fp16 operands for attention) ---
    hgemm_kernel<1><<<dim3(INNER / 64, (NB * NQ) / 128), 256>>>(
        x16, WqTh, WqTl, nullptr, nullptr, Qh, nullptr, NB * NQ, DQ, INNER);
    hgemm_kernel<2><<<dim3(INNER / 64, (NB * NKK) / 128), 256>>>(
        c16, WkTh, WkTl, nullptr, nullptr, Kh, Kl, NB * NKK, DC, INNER);
    hgemm_kernel<3><<<dim3(INNER / 64, (NB * NKK) / 128), 256>>>(
        c16, WvTh, WvTl, nullptr, nullptr, Vth, nullptr, NB * NKK, DC, INNER);

    // --- fused attention on tensor cores ---
    attn_mma_kernel<<<dim3(NQ / 128, NB * NHEAD), 256, ATT_BYTES>>>(
        Qh, Kh, Kl, Vth, AO16);

    // --- output projection (+bias) ---
    hgemm_kernel<0><<<dim3(DQ / 64, (NB * NQ) / 128), 256>>>(
        AO16, WoTh, WoTl, bo, out, nullptr, nullptr, NB * NQ, INNER, DQ);
}